// round 3
// baseline (speedup 1.0000x reference)
#include <cuda_runtime.h>
#include <cstdint>
#include <cmath>

// ----------------------------------------------------------------------------
// CGRU cell, B=1024, UNITS=2048.
//   X   = inputs @ Kcat            (1024 x 12288)   Kcat virtual from rk/ik
//   HZR = h_tm1  @ [Rz|Rr]         (1024 x 8192)
//   z,r = hard_sigmoid(X[:,g]+b_g+HZR[:,g]) ; RH = r*h
//   HH  = RH @ Rh                  (1024 x 4096)
//   out = z*h + (1-z)*tanh(X[:,h]+b_h+HH)
// GEMMs in TF32 mma.sync with fp32 accumulate.
// ----------------------------------------------------------------------------

#define UNITS 2048
#define Kdim  4096
#define WLD   6144   // row stride of weight matrices (3*UNITS)

// scratch (device globals: allocation-free)
__device__ float g_X  [(size_t)1024 * 12288];
__device__ float g_HZR[(size_t)1024 * 8192];
__device__ float g_Z  [(size_t)1024 * 4096];
__device__ float g_RH [(size_t)1024 * 4096];
__device__ float g_HH [(size_t)1024 * 4096];

__device__ __forceinline__ uint32_t f2tf32(float x) {
    uint32_t r;
    asm("cvt.rna.tf32.f32 %0, %1;" : "=r"(r) : "f"(x));
    return r;
}

__device__ __forceinline__ void cp16(float* dst, const float* src) {
    uint32_t s = (uint32_t)__cvta_generic_to_shared(dst);
    asm volatile("cp.async.cg.shared.global [%0], [%1], 16;" :: "r"(s), "l"(src));
}

__device__ __forceinline__ void mma_tf32(float* c, const uint32_t* a, const uint32_t* b) {
    asm volatile(
        "mma.sync.aligned.m16n8k8.row.col.f32.tf32.tf32.f32 "
        "{%0,%1,%2,%3},{%4,%5,%6,%7},{%8,%9},{%0,%1,%2,%3};"
        : "+f"(c[0]), "+f"(c[1]), "+f"(c[2]), "+f"(c[3])
        : "r"(a[0]), "r"(a[1]), "r"(a[2]), "r"(a[3]), "r"(b[0]), "r"(b[1]));
}

#define BM 128
#define BN 128
#define BK 32
#define ALD 36     // padded A row stride (floats)
#define BLD 136    // padded B row stride (floats)
#define ASTG (BM * ALD)
#define BSTG (BK * BLD)
#define SMEM_FLOATS (2 * ASTG + 2 * BSTG)
#define SMEM_BYTES (SMEM_FLOATS * 4)

// C[m, n] = sum_k A[m, k] * Bvirt[k, n]
// Bvirt per gate g = gate_base + n/4096, nn = n % 4096:
//   nn <  2048: k<2048 -> Wr[k, g*2048+nn]          ; k>=2048 ->  Wi[k-2048, ...]
//   nn >= 2048: k<2048 -> -Wi[k, g*2048+(nn-2048)]  ; k>=2048 ->  Wr[k-2048, ...]
__global__ __launch_bounds__(256, 2) void gemm_cgru(
    const float* __restrict__ A, const float* __restrict__ Wr,
    const float* __restrict__ Wi, float* __restrict__ C,
    int N, int gate_base)
{
    extern __shared__ float sm[];
    float* AsBuf[2] = { sm, sm + ASTG };
    float* BsBuf[2] = { sm + 2 * ASTG, sm + 2 * ASTG + BSTG };

    const int tid   = threadIdx.x;
    const int nBase = blockIdx.x * BN;
    const int mBase = blockIdx.y * BM;

    const int  gate      = gate_base + (nBase >> 12);
    const int  n_in_gate = nBase & 4095;
    const bool half_n    = (n_in_gate >= UNITS);
    const int  wcol      = gate * UNITS + (n_in_gate & (UNITS - 1));

    const float* Abase = A + (size_t)mBase * Kdim;

    auto load_stage = [&](int kb, int s) {
        const int kBase = kb * BK;
        const float* Ar = Abase + kBase;
#pragma unroll
        for (int i = 0; i < 4; i++) {
            int c = tid + i * 256;
            int r = c >> 3, co = (c & 7) << 2;
            cp16(&AsBuf[s][r * ALD + co], Ar + (size_t)r * Kdim + co);
        }
        const bool half_k = (kBase >= UNITS);
        const float* W = (half_k == half_n) ? Wr : Wi;
        const float* Bsrc = W + (size_t)(kBase & (UNITS - 1)) * WLD + wcol;
#pragma unroll
        for (int i = 0; i < 4; i++) {
            int c = tid + i * 256;
            int kk = c >> 5, no = (c & 31) << 2;
            cp16(&BsBuf[s][kk * BLD + no], Bsrc + (size_t)kk * WLD + no);
        }
        asm volatile("cp.async.commit_group;");
    };

    const int wid  = tid >> 5;
    const int lane = tid & 31;
    const int wm   = (wid & 1) * 64;
    const int wn   = (wid >> 1) * 32;
    const int grp  = lane >> 2;
    const int tig  = lane & 3;

    float acc[4][4][4];
#pragma unroll
    for (int a = 0; a < 4; a++)
#pragma unroll
        for (int b = 0; b < 4; b++)
#pragma unroll
            for (int c = 0; c < 4; c++) acc[a][b][c] = 0.0f;

    const int ITERS = Kdim / BK; // 128
    load_stage(0, 0);

    for (int kb = 0; kb < ITERS; ++kb) {
        const int cur = kb & 1;
        if (kb + 1 < ITERS) {
            load_stage(kb + 1, cur ^ 1);
            asm volatile("cp.async.wait_group 1;");
        } else {
            asm volatile("cp.async.wait_group 0;");
        }
        __syncthreads();

        const float sign = (half_n && (kb < (UNITS / BK))) ? -1.0f : 1.0f;
        const float* Ap = AsBuf[cur];
        const float* Bp = BsBuf[cur];

#pragma unroll
        for (int ks = 0; ks < 4; ++ks) {
            const int k0 = ks * 8;
            uint32_t af[4][4];
#pragma unroll
            for (int tm = 0; tm < 4; ++tm) {
                const int r = wm + tm * 16 + grp;
                af[tm][0] = f2tf32(Ap[r * ALD + k0 + tig]);
                af[tm][1] = f2tf32(Ap[(r + 8) * ALD + k0 + tig]);
                af[tm][2] = f2tf32(Ap[r * ALD + k0 + tig + 4]);
                af[tm][3] = f2tf32(Ap[(r + 8) * ALD + k0 + tig + 4]);
            }
            uint32_t bfr[4][2];
#pragma unroll
            for (int tn = 0; tn < 4; ++tn) {
                const int cn = wn + tn * 8 + grp;
                bfr[tn][0] = f2tf32(sign * Bp[(k0 + tig) * BLD + cn]);
                bfr[tn][1] = f2tf32(sign * Bp[(k0 + tig + 4) * BLD + cn]);
            }
#pragma unroll
            for (int tm = 0; tm < 4; ++tm)
#pragma unroll
                for (int tn = 0; tn < 4; ++tn)
                    mma_tf32(acc[tm][tn], af[tm], bfr[tn]);
        }
        __syncthreads();
    }

    // epilogue
#pragma unroll
    for (int tm = 0; tm < 4; ++tm) {
#pragma unroll
        for (int tn = 0; tn < 4; ++tn) {
            const int m0 = mBase + wm + tm * 16 + grp;
            const int n0 = nBase + wn + tn * 8 + tig * 2;
            *(float2*)&C[(size_t)m0 * N + n0]       = make_float2(acc[tm][tn][0], acc[tm][tn][1]);
            *(float2*)&C[(size_t)(m0 + 8) * N + n0] = make_float2(acc[tm][tn][2], acc[tm][tn][3]);
        }
    }
}

__device__ __forceinline__ float hsig(float x) {
    return fminf(fmaxf(0.2f * x + 0.5f, 0.0f), 1.0f);
}

// z/r gates + r*h
__global__ void ew_zr(const float* __restrict__ X, const float* __restrict__ HZR,
                      const float* __restrict__ h, const float* __restrict__ rb,
                      const float* __restrict__ ib, float* __restrict__ Z,
                      float* __restrict__ RH)
{
    const int i = blockIdx.x * blockDim.x + threadIdx.x;  // float4 index, 1024*1024 total
    const int m = i >> 10;
    const int n = (i & 1023) << 2;

    const float4 xz = *(const float4*)&X[(size_t)m * 12288 + n];
    const float4 xr = *(const float4*)&X[(size_t)m * 12288 + 4096 + n];
    const float4 hz = *(const float4*)&HZR[(size_t)m * 8192 + n];
    const float4 hr = *(const float4*)&HZR[(size_t)m * 8192 + 4096 + n];
    const float4 hv = *(const float4*)&h[(size_t)m * 4096 + n];

    const float* bsel = (n < UNITS) ? rb : ib;
    const int bo = n & (UNITS - 1);
    const float4 bz = *(const float4*)&bsel[bo];           // gate z
    const float4 br = *(const float4*)&bsel[UNITS + bo];   // gate r

    float4 zv, rhv;
    zv.x = hsig(xz.x + bz.x + hz.x);
    zv.y = hsig(xz.y + bz.y + hz.y);
    zv.z = hsig(xz.z + bz.z + hz.z);
    zv.w = hsig(xz.w + bz.w + hz.w);
    rhv.x = hsig(xr.x + br.x + hr.x) * hv.x;
    rhv.y = hsig(xr.y + br.y + hr.y) * hv.y;
    rhv.z = hsig(xr.z + br.z + hr.z) * hv.z;
    rhv.w = hsig(xr.w + br.w + hr.w) * hv.w;

    *(float4*)&Z[(size_t)m * 4096 + n]  = zv;
    *(float4*)&RH[(size_t)m * 4096 + n] = rhv;
}

// final blend
__global__ void ew_out(const float* __restrict__ X, const float* __restrict__ HH,
                       const float* __restrict__ h, const float* __restrict__ rb,
                       const float* __restrict__ ib, const float* __restrict__ Z,
                       float* __restrict__ out)
{
    const int i = blockIdx.x * blockDim.x + threadIdx.x;
    const int m = i >> 10;
    const int n = (i & 1023) << 2;

    const float4 xh = *(const float4*)&X[(size_t)m * 12288 + 8192 + n];
    const float4 hhv = *(const float4*)&HH[(size_t)m * 4096 + n];
    const float4 hv  = *(const float4*)&h[(size_t)m * 4096 + n];
    const float4 zv  = *(const float4*)&Z[(size_t)m * 4096 + n];

    const float* bsel = (n < UNITS) ? rb : ib;
    const int bo = n & (UNITS - 1);
    const float4 bh = *(const float4*)&bsel[2 * UNITS + bo];  // gate h

    float4 o;
    o.x = zv.x * hv.x + (1.0f - zv.x) * tanhf(xh.x + bh.x + hhv.x);
    o.y = zv.y * hv.y + (1.0f - zv.y) * tanhf(xh.y + bh.y + hhv.y);
    o.z = zv.z * hv.z + (1.0f - zv.z) * tanhf(xh.z + bh.z + hhv.z);
    o.w = zv.w * hv.w + (1.0f - zv.w) * tanhf(xh.w + bh.w + hhv.w);

    *(float4*)&out[(size_t)m * 4096 + n] = o;
}

extern "C" void kernel_launch(void* const* d_in, const int* in_sizes, int n_in,
                              void* d_out, int out_size)
{
    const float* inputs = (const float*)d_in[0];
    const float* h_tm1  = (const float*)d_in[1];
    const float* rk     = (const float*)d_in[2];
    const float* ik     = (const float*)d_in[3];
    const float* rrk    = (const float*)d_in[4];
    const float* irk    = (const float*)d_in[5];
    const float* rb     = (const float*)d_in[6];
    const float* ib     = (const float*)d_in[7];
    float* out = (float*)d_out;

    float *pX, *pHZR, *pZ, *pRH, *pHH;
    cudaGetSymbolAddress((void**)&pX,   g_X);
    cudaGetSymbolAddress((void**)&pHZR, g_HZR);
    cudaGetSymbolAddress((void**)&pZ,   g_Z);
    cudaGetSymbolAddress((void**)&pRH,  g_RH);
    cudaGetSymbolAddress((void**)&pHH,  g_HH);

    cudaFuncSetAttribute(gemm_cgru, cudaFuncAttributeMaxDynamicSharedMemorySize, SMEM_BYTES);

    dim3 blk(256);
    // X = inputs @ Kcat  (3 gates, N=12288)
    gemm_cgru<<<dim3(96, 8), blk, SMEM_BYTES>>>(inputs, rk, ik, pX, 12288, 0);
    // HZR = h @ [Rz|Rr]  (gates z,r, N=8192)
    gemm_cgru<<<dim3(64, 8), blk, SMEM_BYTES>>>(h_tm1, rrk, irk, pHZR, 8192, 0);
    // z, r, r*h
    ew_zr<<<4096, 256>>>(pX, pHZR, h_tm1, rb, ib, pZ, pRH);
    // HH = (r*h) @ Rh    (gate h only, N=4096, gate_base=2)
    gemm_cgru<<<dim3(32, 8), blk, SMEM_BYTES>>>(pRH, rrk, irk, pHH, 4096, 2);
    // out = z*h + (1-z)*tanh(...)
    ew_out<<<4096, 256>>>(pX, pHH, h_tm1, rb, ib, pZ, out);
}

// round 5
// speedup vs baseline: 1.3798x; 1.3798x over previous
#include <cuda_runtime.h>
#include <cstdint>
#include <cmath>

// ============================================================================
// CGRU cell, B=1024, UNITS=2048 — fragment-layout TF32 mma.sync pipeline.
// Virtual complex weights [[Wr,-Wi],[Wi,Wr]] are materialized ONCE per launch
// into MMA-fragment order (sign + tf32-RNA rounding folded in), so the GEMM
// inner loop is pure LDS.128 + HMMA.
// ============================================================================

#define UNITS 2048
#define Kdim  4096
#define WLD   6144
#define TILE_F 4096            // floats per 128x32 (or 32x128) tile = 16KB

// ------------------------------ scratch (device globals, allocation-free) --
__device__ float g_BK [(size_t)96 * 128 * TILE_F];   // Kcat'  (201MB)
__device__ float g_BR [(size_t)96 * 128 * TILE_F];   // Rcat'  (201MB)
__device__ float g_Ap [(size_t)8  * 128 * TILE_F];   // inputs' (16MB)
__device__ float g_Hp [(size_t)8  * 128 * TILE_F];   // h'      (16MB)
__device__ float g_RHp[(size_t)8  * 128 * TILE_F];   // (r*h)'  (16MB)
__device__ float g_X  [(size_t)1024 * 12288];
__device__ float g_HZR[(size_t)1024 * 8192];
__device__ float g_Z  [(size_t)1024 * 4096];
__device__ float g_HH [(size_t)1024 * 4096];

// ----------------------------------------------------------------- helpers --
__device__ __forceinline__ float rndtf32(float x) {
    uint32_t u;
    asm("cvt.rna.tf32.f32 %0, %1;" : "=r"(u) : "f"(x));
    return __uint_as_float(u);
}
__device__ __forceinline__ void cp16s(uint32_t d, const float* s) {
    asm volatile("cp.async.cg.shared.global [%0], [%1], 16;" :: "r"(d), "l"(s));
}
__device__ __forceinline__ uint32_t smem_u32(const void* p) {
    uint32_t a;
    asm("{ .reg .u64 t; cvta.to.shared.u64 t, %1; cvt.u32.u64 %0, t; }" : "=r"(a) : "l"(p));
    return a;
}
__device__ __forceinline__ void mma_tf32(float* c, const uint32_t* a, uint32_t b0, uint32_t b1) {
    asm volatile(
        "mma.sync.aligned.m16n8k8.row.col.f32.tf32.tf32.f32 "
        "{%0,%1,%2,%3},{%4,%5,%6,%7},{%8,%9},{%0,%1,%2,%3};"
        : "+f"(c[0]), "+f"(c[1]), "+f"(c[2]), "+f"(c[3])
        : "r"(a[0]), "r"(a[1]), "r"(a[2]), "r"(a[3]), "r"(b0), "r"(b1));
}

// ============================================================================
// prep_w: build fragment-layout virtual weight panels for Kcat' and Rcat'.
// Dest float4 index decomposition (per matrix, 96 panels x 128 kb x 1024 f4):
//   tile f4 x: q = x>>5 (= ks*8 + n16), lane = x&31 (= grp*4 + tig)
//   slots: (n8=0,kh=0),(0,1),(1,0),(1,1) -> W[k][col], W[k+4][col], W[k][col+8], W[k+4][col+8]
// ============================================================================
__global__ void prep_w(const float* __restrict__ rk,  const float* __restrict__ ik,
                       const float* __restrict__ rrk, const float* __restrict__ irk)
{
    const size_t PER = (size_t)96 * 128 * 1024;      // float4s per matrix
    size_t fidx = (size_t)blockIdx.x * blockDim.x + threadIdx.x;
    const int mat = fidx >= PER;
    size_t loc = fidx - (size_t)mat * PER;

    const int panel = (int)(loc >> 17);
    const int rest  = (int)(loc & 131071);
    const int kb    = rest >> 10;
    const int x     = rest & 1023;
    const int q     = x >> 5, lane = x & 31;
    const int ks = q >> 3, n16 = q & 7;
    const int grp = lane >> 2, tig = lane & 3;

    const int k      = kb * 32 + ks * 8 + tig;
    const int gate   = panel >> 5;
    const int nig    = ((panel & 31) << 7) + (n16 << 4) + grp;
    const bool half_n = nig >= UNITS;
    const int col    = gate * UNITS + (nig & (UNITS - 1));
    const bool half_k = k >= UNITS;
    const int row    = k & (UNITS - 1);

    const float* Wr = mat ? rrk : rk;
    const float* Wi = mat ? irk : ik;
    const float* W  = (half_k == half_n) ? Wr : Wi;
    const float  s  = (half_n && !half_k) ? -1.0f : 1.0f;

    float v0 = W[(size_t)row * WLD + col];
    float v1 = W[(size_t)(row + 4) * WLD + col];
    float v2 = W[(size_t)row * WLD + col + 8];
    float v3 = W[(size_t)(row + 4) * WLD + col + 8];

    float* out = mat ? g_BR : g_BK;
    ((float4*)out)[loc] = make_float4(rndtf32(s * v0), rndtf32(s * v1),
                                      rndtf32(s * v2), rndtf32(s * v3));
}

// ============================================================================
// prep_a: inputs' and h' in fragment layout.
//   slots: (a0,a1,a2,a3) = A[m][k], A[m+8][k], A[m][k+4], A[m+8][k+4]
// ============================================================================
__global__ void prep_a(const float* __restrict__ in0, const float* __restrict__ in1)
{
    const size_t PER = (size_t)8 * 128 * 1024;
    size_t fidx = (size_t)blockIdx.x * blockDim.x + threadIdx.x;
    const int mat = fidx >= PER;
    size_t loc = fidx - (size_t)mat * PER;

    const int mp   = (int)(loc >> 17);
    const int rest = (int)(loc & 131071);
    const int kb   = rest >> 10;
    const int x    = rest & 1023;
    const int q = x >> 5, lane = x & 31;
    const int ks = q >> 3, m16 = q & 7;
    const int grp = lane >> 2, tig = lane & 3;

    const int m = mp * 128 + m16 * 16 + grp;
    const int k = kb * 32 + ks * 8 + tig;
    const float* A = mat ? in1 : in0;

    float a0 = A[(size_t)m * Kdim + k];
    float a1 = A[(size_t)(m + 8) * Kdim + k];
    float a2 = A[(size_t)m * Kdim + k + 4];
    float a3 = A[(size_t)(m + 8) * Kdim + k + 4];

    float* out = mat ? g_Hp : g_Ap;
    ((float4*)out)[loc] = make_float4(rndtf32(a0), rndtf32(a1), rndtf32(a2), rndtf32(a3));
}

// ============================================================================
// gemm_frag: C[1024 x Nld] tile (128x128) from fragment-layout A' and B'.
// 256 threads, 8 warps of 64x32, BK=32, 3-stage cp.async pipeline.
// ============================================================================
#define STAGES 3
#define STG_BYTES (2 * TILE_F * 4)           // 32KB per stage
#define GSMEM (STAGES * STG_BYTES)           // 96KB

__global__ __launch_bounds__(256, 2) void gemm_frag(
    const float* __restrict__ Ap, const float* __restrict__ Bp,
    float* __restrict__ C, int Nld)
{
    extern __shared__ float sm[];
    const uint32_t sbase = smem_u32(sm);
    const int tid = threadIdx.x, wid = tid >> 5, lane = tid & 31;
    const int grp = lane >> 2, tig = lane & 3;
    const int mp = blockIdx.y;
    const int panel = blockIdx.x;

    const float* At = Ap + (size_t)mp * 128 * TILE_F;
    const float* Bt = Bp + (size_t)panel * 128 * TILE_F;

    const int wm16 = (wid & 1) * 4;      // A m16-block base
    const int wn16 = (wid >> 1) * 2;     // B n16-block base

    float acc[4][4][4];
#pragma unroll
    for (int a = 0; a < 4; a++)
#pragma unroll
        for (int b = 0; b < 4; b++)
#pragma unroll
            for (int c = 0; c < 4; c++) acc[a][b][c] = 0.0f;

    #define ISSUE(kb) do {                                                     \
        const uint32_t _st = sbase + ((kb) % STAGES) * STG_BYTES;              \
        const float* _sa = At + (size_t)(kb) * TILE_F;                         \
        const float* _sb = Bt + (size_t)(kb) * TILE_F;                         \
        _Pragma("unroll")                                                      \
        for (int _i = 0; _i < 4; _i++) {                                       \
            const int _o = (tid + _i * 256) * 4;                               \
            cp16s(_st + _o * 4, _sa + _o);                                     \
            cp16s(_st + 16384 + _o * 4, _sb + _o);                             \
        }                                                                      \
    } while (0)

#pragma unroll
    for (int p = 0; p < STAGES; p++) {
        ISSUE(p);
        asm volatile("cp.async.commit_group;" ::: "memory");
    }

    for (int kb = 0; kb < 128; ++kb) {
        asm volatile("cp.async.wait_group %0;" :: "n"(STAGES - 1) : "memory");
        __syncthreads();

        const float* As = sm + (kb % STAGES) * 2 * TILE_F;
        const float* Bs = As + TILE_F;

#pragma unroll
        for (int ks = 0; ks < 4; ++ks) {
            float4 af[4], bf[2];
#pragma unroll
            for (int tm = 0; tm < 4; ++tm)
                af[tm] = *(const float4*)(As + ((ks * 8 + wm16 + tm) << 7) + (lane << 2));
#pragma unroll
            for (int p = 0; p < 2; ++p)
                bf[p] = *(const float4*)(Bs + ((ks * 8 + wn16 + p) << 7) + (lane << 2));
#pragma unroll
            for (int tm = 0; tm < 4; ++tm) {
                const uint32_t* a = (const uint32_t*)&af[tm];
#pragma unroll
                for (int tn = 0; tn < 4; ++tn) {
                    const uint32_t* bu = (const uint32_t*)&bf[tn >> 1];
                    mma_tf32(acc[tm][tn], a, bu[(tn & 1) * 2], bu[(tn & 1) * 2 + 1]);
                }
            }
        }
        __syncthreads();

        if (kb + STAGES < 128) ISSUE(kb + STAGES);
        asm volatile("cp.async.commit_group;" ::: "memory");
    }

    // epilogue (round-1 proven mapping)
#pragma unroll
    for (int tm = 0; tm < 4; ++tm) {
#pragma unroll
        for (int tn = 0; tn < 4; ++tn) {
            const int m0 = mp * 128 + (wid & 1) * 64 + tm * 16 + grp;
            const int n0 = panel * 128 + (wid >> 1) * 32 + tn * 8 + tig * 2;
            *(float2*)&C[(size_t)m0 * Nld + n0]       = make_float2(acc[tm][tn][0], acc[tm][tn][1]);
            *(float2*)&C[(size_t)(m0 + 8) * Nld + n0] = make_float2(acc[tm][tn][2], acc[tm][tn][3]);
        }
    }
}

// ---------------------------------------------------------------- elementwise
__device__ __forceinline__ float hsig(float x) {
    return fminf(fmaxf(0.2f * x + 0.5f, 0.0f), 1.0f);
}

// z/r gates; Z canonical, RH written directly into fragment layout (GEMM A').
__global__ void ew_zr(const float* __restrict__ X, const float* __restrict__ HZR,
                      const float* __restrict__ h, const float* __restrict__ rb,
                      const float* __restrict__ ib, float* __restrict__ Z,
                      float* __restrict__ RHp)
{
    const int i = blockIdx.x * blockDim.x + threadIdx.x;
    const int m = i >> 10;
    const int n = (i & 1023) << 2;

    const float4 xz = *(const float4*)&X[(size_t)m * 12288 + n];
    const float4 xr = *(const float4*)&X[(size_t)m * 12288 + 4096 + n];
    const float4 hz = *(const float4*)&HZR[(size_t)m * 8192 + n];
    const float4 hr = *(const float4*)&HZR[(size_t)m * 8192 + 4096 + n];
    const float4 hv = *(const float4*)&h[(size_t)m * 4096 + n];

    const float* bsel = (n < UNITS) ? rb : ib;
    const int bo = n & (UNITS - 1);
    const float4 bz = *(const float4*)&bsel[bo];
    const float4 br = *(const float4*)&bsel[UNITS + bo];

    float4 zv;
    zv.x = hsig(xz.x + bz.x + hz.x);  zv.y = hsig(xz.y + bz.y + hz.y);
    zv.z = hsig(xz.z + bz.z + hz.z);  zv.w = hsig(xz.w + bz.w + hz.w);
    float rh0 = rndtf32(hsig(xr.x + br.x + hr.x) * hv.x);
    float rh1 = rndtf32(hsig(xr.y + br.y + hr.y) * hv.y);
    float rh2 = rndtf32(hsig(xr.z + br.z + hr.z) * hv.z);
    float rh3 = rndtf32(hsig(xr.w + br.w + hr.w) * hv.w);

    *(float4*)&Z[(size_t)m * 4096 + n] = zv;

    // fragment-layout scatter for RH' (this thread covers tig=0..3 of one slot)
    const int mp = m >> 7, m16 = (m >> 4) & 7, j = m & 15;
    const int grp = j & 7, hi = j >> 3;
    const int kb = n >> 5, ks = (n >> 3) & 3, kh = (n >> 2) & 1;
    float* base = RHp + ((size_t)(mp * 128 + kb)) * TILE_F
                + ((ks * 8 + m16) << 7) + (grp << 4) + (hi + (kh << 1));
    base[0]  = rh0;
    base[4]  = rh1;
    base[8]  = rh2;
    base[12] = rh3;
}

__global__ void ew_out(const float* __restrict__ X, const float* __restrict__ HH,
                       const float* __restrict__ h, const float* __restrict__ rb,
                       const float* __restrict__ ib, const float* __restrict__ Z,
                       float* __restrict__ out)
{
    const int i = blockIdx.x * blockDim.x + threadIdx.x;
    const int m = i >> 10;
    const int n = (i & 1023) << 2;

    const float4 xh  = *(const float4*)&X[(size_t)m * 12288 + 8192 + n];
    const float4 hhv = *(const float4*)&HH[(size_t)m * 4096 + n];
    const float4 hv  = *(const float4*)&h[(size_t)m * 4096 + n];
    const float4 zv  = *(const float4*)&Z[(size_t)m * 4096 + n];

    const float* bsel = (n < UNITS) ? rb : ib;
    const int bo = n & (UNITS - 1);
    const float4 bh = *(const float4*)&bsel[2 * UNITS + bo];

    float4 o;
    o.x = zv.x * hv.x + (1.0f - zv.x) * tanhf(xh.x + bh.x + hhv.x);
    o.y = zv.y * hv.y + (1.0f - zv.y) * tanhf(xh.y + bh.y + hhv.y);
    o.z = zv.z * hv.z + (1.0f - zv.z) * tanhf(xh.z + bh.z + hhv.z);
    o.w = zv.w * hv.w + (1.0f - zv.w) * tanhf(xh.w + bh.w + hhv.w);

    *(float4*)&out[(size_t)m * 4096 + n] = o;
}

// --------------------------------------------------------------------- launch
extern "C" void kernel_launch(void* const* d_in, const int* in_sizes, int n_in,
                              void* d_out, int out_size)
{
    const float* inputs = (const float*)d_in[0];
    const float* h_tm1  = (const float*)d_in[1];
    const float* rk     = (const float*)d_in[2];
    const float* ik     = (const float*)d_in[3];
    const float* rrk    = (const float*)d_in[4];
    const float* irk    = (const float*)d_in[5];
    const float* rb     = (const float*)d_in[6];
    const float* ib     = (const float*)d_in[7];
    float* out = (float*)d_out;

    float *pBK, *pBR, *pAp, *pHp, *pRHp, *pX, *pHZR, *pZ, *pHH;
    cudaGetSymbolAddress((void**)&pBK,  g_BK);
    cudaGetSymbolAddress((void**)&pBR,  g_BR);
    cudaGetSymbolAddress((void**)&pAp,  g_Ap);
    cudaGetSymbolAddress((void**)&pHp,  g_Hp);
    cudaGetSymbolAddress((void**)&pRHp, g_RHp);
    cudaGetSymbolAddress((void**)&pX,   g_X);
    cudaGetSymbolAddress((void**)&pHZR, g_HZR);
    cudaGetSymbolAddress((void**)&pZ,   g_Z);
    cudaGetSymbolAddress((void**)&pHH,  g_HH);

    cudaFuncSetAttribute(gemm_frag, cudaFuncAttributeMaxDynamicSharedMemorySize, GSMEM);

    // materialize fragment-layout operands
    prep_w<<<98304, 256>>>(rk, ik, rrk, irk);
    prep_a<<<8192, 256>>>(inputs, h_tm1);

    // X = inputs @ Kcat   (N = 12288)
    gemm_frag<<<dim3(96, 8), 256, GSMEM>>>(pAp, pBK, pX, 12288);
    // HZR = h @ [Rz|Rr]   (N = 8192, Rcat' panels 0..63)
    gemm_frag<<<dim3(64, 8), 256, GSMEM>>>(pHp, pBR, pHZR, 8192);
    // gates + RH' (fragment layout)
    ew_zr<<<4096, 256>>>(pX, pHZR, h_tm1, rb, ib, pZ, pRHp);
    // HH = (r*h) @ Rh     (N = 4096, Rcat' panels 64..95)
    gemm_frag<<<dim3(32, 8), 256, GSMEM>>>(pRHp, pBR + (size_t)64 * 128 * TILE_F, pHH, 4096);
    // out
    ew_out<<<4096, 256>>>(pX, pHH, h_tm1, rb, ib, pZ, out);
}

// round 6
// speedup vs baseline: 1.5542x; 1.1264x over previous
#include <cuda_runtime.h>
#include <cstdint>
#include <cmath>

// ============================================================================
// CGRU cell, B=1024, UNITS=2048 — fragment-layout TF32 mma.sync pipeline v2.
// Weights materialized once into MMA-fragment order (sign + tf32-RNA folded).
// GEMM: 128x128 CTA tile, 4 warps of 64x64, BK=32, 3-stage cp.async,
// one __syncthreads per BK, register double-buffered fragments.
// ============================================================================

#define UNITS 2048
#define Kdim  4096
#define WLD   6144
#define TILE_F 4096            // floats per 128x32 (or 32x128) tile = 16KB

// ------------------------------ scratch (device globals, allocation-free) --
__device__ float g_BK [(size_t)96 * 128 * TILE_F];   // Kcat'  (201MB)
__device__ float g_BR [(size_t)96 * 128 * TILE_F];   // Rcat'  (201MB)
__device__ float g_Ap [(size_t)8  * 128 * TILE_F];   // inputs' (16MB)
__device__ float g_Hp [(size_t)8  * 128 * TILE_F];   // h'      (16MB)
__device__ float g_RHp[(size_t)8  * 128 * TILE_F];   // (r*h)'  (16MB)
__device__ float g_X  [(size_t)1024 * 12288];
__device__ float g_HZR[(size_t)1024 * 8192];
__device__ float g_Z  [(size_t)1024 * 4096];
__device__ float g_HH [(size_t)1024 * 4096];

// ----------------------------------------------------------------- helpers --
__device__ __forceinline__ float rndtf32(float x) {
    uint32_t u;
    asm("cvt.rna.tf32.f32 %0, %1;" : "=r"(u) : "f"(x));
    return __uint_as_float(u);
}
__device__ __forceinline__ void cp16s(uint32_t d, const float* s) {
    asm volatile("cp.async.cg.shared.global [%0], [%1], 16;" :: "r"(d), "l"(s));
}
__device__ __forceinline__ uint32_t smem_u32(const void* p) {
    uint32_t a;
    asm("{ .reg .u64 t; cvta.to.shared.u64 t, %1; cvt.u32.u64 %0, t; }" : "=r"(a) : "l"(p));
    return a;
}
__device__ __forceinline__ void mma_tf32(float* c, const uint32_t* a, uint32_t b0, uint32_t b1) {
    asm volatile(
        "mma.sync.aligned.m16n8k8.row.col.f32.tf32.tf32.f32 "
        "{%0,%1,%2,%3},{%4,%5,%6,%7},{%8,%9},{%0,%1,%2,%3};"
        : "+f"(c[0]), "+f"(c[1]), "+f"(c[2]), "+f"(c[3])
        : "r"(a[0]), "r"(a[1]), "r"(a[2]), "r"(a[3]), "r"(b0), "r"(b1));
}

// ============================================================================
// prep_w: fragment-layout virtual weight panels (unchanged from round 5).
// ============================================================================
__global__ void prep_w(const float* __restrict__ rk,  const float* __restrict__ ik,
                       const float* __restrict__ rrk, const float* __restrict__ irk)
{
    const size_t PER = (size_t)96 * 128 * 1024;
    size_t fidx = (size_t)blockIdx.x * blockDim.x + threadIdx.x;
    const int mat = fidx >= PER;
    size_t loc = fidx - (size_t)mat * PER;

    const int panel = (int)(loc >> 17);
    const int rest  = (int)(loc & 131071);
    const int kb    = rest >> 10;
    const int x     = rest & 1023;
    const int q     = x >> 5, lane = x & 31;
    const int ks = q >> 3, n16 = q & 7;
    const int grp = lane >> 2, tig = lane & 3;

    const int k      = kb * 32 + ks * 8 + tig;
    const int gate   = panel >> 5;
    const int nig    = ((panel & 31) << 7) + (n16 << 4) + grp;
    const bool half_n = nig >= UNITS;
    const int col    = gate * UNITS + (nig & (UNITS - 1));
    const bool half_k = k >= UNITS;
    const int row    = k & (UNITS - 1);

    const float* Wr = mat ? rrk : rk;
    const float* Wi = mat ? irk : ik;
    const float* W  = (half_k == half_n) ? Wr : Wi;
    const float  s  = (half_n && !half_k) ? -1.0f : 1.0f;

    float v0 = W[(size_t)row * WLD + col];
    float v1 = W[(size_t)(row + 4) * WLD + col];
    float v2 = W[(size_t)row * WLD + col + 8];
    float v3 = W[(size_t)(row + 4) * WLD + col + 8];

    float* out = mat ? g_BR : g_BK;
    ((float4*)out)[loc] = make_float4(rndtf32(s * v0), rndtf32(s * v1),
                                      rndtf32(s * v2), rndtf32(s * v3));
}

// ============================================================================
// prep_a: inputs' and h' in fragment layout (unchanged).
// ============================================================================
__global__ void prep_a(const float* __restrict__ in0, const float* __restrict__ in1)
{
    const size_t PER = (size_t)8 * 128 * 1024;
    size_t fidx = (size_t)blockIdx.x * blockDim.x + threadIdx.x;
    const int mat = fidx >= PER;
    size_t loc = fidx - (size_t)mat * PER;

    const int mp   = (int)(loc >> 17);
    const int rest = (int)(loc & 131071);
    const int kb   = rest >> 10;
    const int x    = rest & 1023;
    const int q = x >> 5, lane = x & 31;
    const int ks = q >> 3, m16 = q & 7;
    const int grp = lane >> 2, tig = lane & 3;

    const int m = mp * 128 + m16 * 16 + grp;
    const int k = kb * 32 + ks * 8 + tig;
    const float* A = mat ? in1 : in0;

    float a0 = A[(size_t)m * Kdim + k];
    float a1 = A[(size_t)(m + 8) * Kdim + k];
    float a2 = A[(size_t)m * Kdim + k + 4];
    float a3 = A[(size_t)(m + 8) * Kdim + k + 4];

    float* out = mat ? g_Hp : g_Ap;
    ((float4*)out)[loc] = make_float4(rndtf32(a0), rndtf32(a1), rndtf32(a2), rndtf32(a3));
}

// ============================================================================
// gemm_frag v2: 128x128 CTA tile, 4 warps of 64x64, single sync per BK.
// ============================================================================
#define STAGES 3
#define STG_F (2 * TILE_F)                 // 8192 floats = 32KB per stage
#define STG_BYTES (STG_F * 4)
#define GSMEM (STAGES * STG_BYTES)         // 96KB

__global__ __launch_bounds__(128, 2) void gemm_frag(
    const float* __restrict__ Ap, const float* __restrict__ Bp,
    float* __restrict__ C, int Nld)
{
    extern __shared__ float sm[];
    const uint32_t sbase = smem_u32(sm);
    const int tid = threadIdx.x, wid = tid >> 5, lane = tid & 31;
    const int grp = lane >> 2, tig = lane & 3;
    const int mp = blockIdx.y;
    const int panel = blockIdx.x;

    const float* At = Ap + (size_t)mp * 128 * TILE_F;
    const float* Bt = Bp + (size_t)panel * 128 * TILE_F;

    const int wm16 = (wid & 1) * 4;      // A m16-unit base (0 or 4)
    const int wn16 = (wid >> 1) * 4;     // B n16-unit base (0 or 4)

    float acc[4][8][4];
#pragma unroll
    for (int a = 0; a < 4; a++)
#pragma unroll
        for (int b = 0; b < 8; b++)
#pragma unroll
            for (int c = 0; c < 4; c++) acc[a][b][c] = 0.0f;

    #define ISSUE(kb) do {                                                     \
        const uint32_t _st = sbase + ((kb) % STAGES) * STG_BYTES;              \
        const float* _sa = At + (size_t)(kb) * TILE_F;                         \
        const float* _sb = Bt + (size_t)(kb) * TILE_F;                         \
        _Pragma("unroll")                                                      \
        for (int _i = 0; _i < 8; _i++) {                                       \
            const int _o = (tid + _i * 128) * 4;                               \
            cp16s(_st + _o * 4, _sa + _o);                                     \
            cp16s(_st + 16384 + _o * 4, _sb + _o);                             \
        }                                                                      \
    } while (0)

    ISSUE(0);
    asm volatile("cp.async.commit_group;" ::: "memory");
    ISSUE(1);
    asm volatile("cp.async.commit_group;" ::: "memory");

    float4 af[2][4], bf[2][4];

    for (int kb = 0; kb < 128; ++kb) {
        asm volatile("cp.async.wait_group 1;" ::: "memory");
        __syncthreads();

        const float* As = sm + (kb % STAGES) * STG_F;
        const float* Bs = As + TILE_F;

        // preload ks=0 fragments
#pragma unroll
        for (int t = 0; t < 4; ++t) {
            af[0][t] = *(const float4*)(As + ((wm16 + t) << 7) + (lane << 2));
            bf[0][t] = *(const float4*)(Bs + ((wn16 + t) << 7) + (lane << 2));
        }

#pragma unroll
        for (int ks = 0; ks < 4; ++ks) {
            const int cur = ks & 1;
            if (ks < 3) {
                const int nx = cur ^ 1, row = (ks + 1) * 8;
#pragma unroll
                for (int t = 0; t < 4; ++t) {
                    af[nx][t] = *(const float4*)(As + ((row + wm16 + t) << 7) + (lane << 2));
                    bf[nx][t] = *(const float4*)(Bs + ((row + wn16 + t) << 7) + (lane << 2));
                }
            }
#pragma unroll
            for (int tm = 0; tm < 4; ++tm) {
                const uint32_t* a = (const uint32_t*)&af[cur][tm];
#pragma unroll
                for (int p = 0; p < 4; ++p) {
                    const uint32_t* bu = (const uint32_t*)&bf[cur][p];
                    mma_tf32(acc[tm][p * 2],     a, bu[0], bu[1]);
                    mma_tf32(acc[tm][p * 2 + 1], a, bu[2], bu[3]);
                }
            }
        }

        if (kb + 2 < 128) ISSUE(kb + 2);
        asm volatile("cp.async.commit_group;" ::: "memory");
    }

    // epilogue
#pragma unroll
    for (int tm = 0; tm < 4; ++tm) {
#pragma unroll
        for (int tn = 0; tn < 8; ++tn) {
            const int m0 = mp * 128 + (wid & 1) * 64 + tm * 16 + grp;
            const int n0 = panel * 128 + (wid >> 1) * 64 + tn * 8 + tig * 2;
            *(float2*)&C[(size_t)m0 * Nld + n0]       = make_float2(acc[tm][tn][0], acc[tm][tn][1]);
            *(float2*)&C[(size_t)(m0 + 8) * Nld + n0] = make_float2(acc[tm][tn][2], acc[tm][tn][3]);
        }
    }
}

// ---------------------------------------------------------------- elementwise
__device__ __forceinline__ float hsig(float x) {
    return fminf(fmaxf(0.2f * x + 0.5f, 0.0f), 1.0f);
}

__global__ void ew_zr(const float* __restrict__ X, const float* __restrict__ HZR,
                      const float* __restrict__ h, const float* __restrict__ rb,
                      const float* __restrict__ ib, float* __restrict__ Z,
                      float* __restrict__ RHp)
{
    const int i = blockIdx.x * blockDim.x + threadIdx.x;
    const int m = i >> 10;
    const int n = (i & 1023) << 2;

    const float4 xz = *(const float4*)&X[(size_t)m * 12288 + n];
    const float4 xr = *(const float4*)&X[(size_t)m * 12288 + 4096 + n];
    const float4 hz = *(const float4*)&HZR[(size_t)m * 8192 + n];
    const float4 hr = *(const float4*)&HZR[(size_t)m * 8192 + 4096 + n];
    const float4 hv = *(const float4*)&h[(size_t)m * 4096 + n];

    const float* bsel = (n < UNITS) ? rb : ib;
    const int bo = n & (UNITS - 1);
    const float4 bz = *(const float4*)&bsel[bo];
    const float4 br = *(const float4*)&bsel[UNITS + bo];

    float4 zv;
    zv.x = hsig(xz.x + bz.x + hz.x);  zv.y = hsig(xz.y + bz.y + hz.y);
    zv.z = hsig(xz.z + bz.z + hz.z);  zv.w = hsig(xz.w + bz.w + hz.w);
    float rh0 = rndtf32(hsig(xr.x + br.x + hr.x) * hv.x);
    float rh1 = rndtf32(hsig(xr.y + br.y + hr.y) * hv.y);
    float rh2 = rndtf32(hsig(xr.z + br.z + hr.z) * hv.z);
    float rh3 = rndtf32(hsig(xr.w + br.w + hr.w) * hv.w);

    *(float4*)&Z[(size_t)m * 4096 + n] = zv;

    const int mp = m >> 7, m16 = (m >> 4) & 7, j = m & 15;
    const int grp = j & 7, hi = j >> 3;
    const int kb = n >> 5, ks = (n >> 3) & 3, kh = (n >> 2) & 1;
    float* base = RHp + ((size_t)(mp * 128 + kb)) * TILE_F
                + ((ks * 8 + m16) << 7) + (grp << 4) + (hi + (kh << 1));
    base[0]  = rh0;
    base[4]  = rh1;
    base[8]  = rh2;
    base[12] = rh3;
}

__global__ void ew_out(const float* __restrict__ X, const float* __restrict__ HH,
                       const float* __restrict__ h, const float* __restrict__ rb,
                       const float* __restrict__ ib, const float* __restrict__ Z,
                       float* __restrict__ out)
{
    const int i = blockIdx.x * blockDim.x + threadIdx.x;
    const int m = i >> 10;
    const int n = (i & 1023) << 2;

    const float4 xh  = *(const float4*)&X[(size_t)m * 12288 + 8192 + n];
    const float4 hhv = *(const float4*)&HH[(size_t)m * 4096 + n];
    const float4 hv  = *(const float4*)&h[(size_t)m * 4096 + n];
    const float4 zv  = *(const float4*)&Z[(size_t)m * 4096 + n];

    const float* bsel = (n < UNITS) ? rb : ib;
    const int bo = n & (UNITS - 1);
    const float4 bh = *(const float4*)&bsel[2 * UNITS + bo];

    float4 o;
    o.x = zv.x * hv.x + (1.0f - zv.x) * tanhf(xh.x + bh.x + hhv.x);
    o.y = zv.y * hv.y + (1.0f - zv.y) * tanhf(xh.y + bh.y + hhv.y);
    o.z = zv.z * hv.z + (1.0f - zv.z) * tanhf(xh.z + bh.z + hhv.z);
    o.w = zv.w * hv.w + (1.0f - zv.w) * tanhf(xh.w + bh.w + hhv.w);

    *(float4*)&out[(size_t)m * 4096 + n] = o;
}

// --------------------------------------------------------------------- launch
extern "C" void kernel_launch(void* const* d_in, const int* in_sizes, int n_in,
                              void* d_out, int out_size)
{
    const float* inputs = (const float*)d_in[0];
    const float* h_tm1  = (const float*)d_in[1];
    const float* rk     = (const float*)d_in[2];
    const float* ik     = (const float*)d_in[3];
    const float* rrk    = (const float*)d_in[4];
    const float* irk    = (const float*)d_in[5];
    const float* rb     = (const float*)d_in[6];
    const float* ib     = (const float*)d_in[7];
    float* out = (float*)d_out;

    float *pBK, *pBR, *pAp, *pHp, *pRHp, *pX, *pHZR, *pZ, *pHH;
    cudaGetSymbolAddress((void**)&pBK,  g_BK);
    cudaGetSymbolAddress((void**)&pBR,  g_BR);
    cudaGetSymbolAddress((void**)&pAp,  g_Ap);
    cudaGetSymbolAddress((void**)&pHp,  g_Hp);
    cudaGetSymbolAddress((void**)&pRHp, g_RHp);
    cudaGetSymbolAddress((void**)&pX,   g_X);
    cudaGetSymbolAddress((void**)&pHZR, g_HZR);
    cudaGetSymbolAddress((void**)&pZ,   g_Z);
    cudaGetSymbolAddress((void**)&pHH,  g_HH);

    cudaFuncSetAttribute(gemm_frag, cudaFuncAttributeMaxDynamicSharedMemorySize, GSMEM);

    prep_w<<<98304, 256>>>(rk, ik, rrk, irk);
    prep_a<<<8192, 256>>>(inputs, h_tm1);

    gemm_frag<<<dim3(96, 8), 128, GSMEM>>>(pAp, pBK, pX, 12288);
    gemm_frag<<<dim3(64, 8), 128, GSMEM>>>(pHp, pBR, pHZR, 8192);
    ew_zr<<<4096, 256>>>(pX, pHZR, h_tm1, rb, ib, pZ, pRHp);
    gemm_frag<<<dim3(32, 8), 128, GSMEM>>>(pRHp, pBR + (size_t)64 * 128 * TILE_F, pHH, 4096);
    ew_out<<<4096, 256>>>(pX, pHH, h_tm1, rb, ib, pZ, out);
}

// round 7
// speedup vs baseline: 2.0328x; 1.3080x over previous
#include <cuda_runtime.h>
#include <cstdint>
#include <cmath>

// ============================================================================
// CGRU cell, B=1024, UNITS=2048 — Gauss 3-mult complex GEMM, TF32 mma.sync.
//   Re(A@conj(W)) = P1 + P2,  Im = P3 + P1 - P2
//   P1 = Ar@Wr, P2 = Ai@Wi, P3 = (Ai-Ar)@(Wr+Wi)   (each K=2048)
// Weights/operands materialized once per launch into MMA-fragment order with
// tf32-RNA rounding folded in. GEMM: 128x128 CTA tile, 4 warps of 64x64,
// BK=32, 64 K-iters, 3-stage cp.async, batched over the 3 Gauss products.
// ============================================================================

#define TILE_F 4096      // floats per 128x32 tile
#define KITERS 64        // 2048 / 32
#define BSTRIDE ((size_t)KITERS * TILE_F)   // 262144 floats per (unit,batch)

// ------------------------------ scratch (device globals, allocation-free) --
__device__ float g_WK [(size_t)48 * 3 * BSTRIDE / 64 * 64]; // 48 panels x 3 batches (151MB)
__device__ float g_WR [(size_t)48 * 3 * BSTRIDE / 64 * 64]; // recurrent (151MB)
__device__ float g_AF [(size_t)8  * 3 * BSTRIDE / 64 * 64]; // inputs' (25MB)
__device__ float g_HF [(size_t)8  * 3 * BSTRIDE / 64 * 64]; // h'      (25MB)
__device__ float g_RHF[(size_t)8  * 3 * BSTRIDE / 64 * 64]; // (r*h)'  (25MB)
__device__ float g_P  [(size_t)3 * 1024 * 6144];            // input-GEMM Ps (75MB)
__device__ float g_Q  [(size_t)3 * 1024 * 4096];            // z,r recurrent Ps
__device__ float g_R  [(size_t)3 * 1024 * 2048];            // h recurrent Ps
__device__ float g_Z  [(size_t)1024 * 4096];

// ----------------------------------------------------------------- helpers --
__device__ __forceinline__ float rndtf32(float x) {
    uint32_t u;
    asm("cvt.rna.tf32.f32 %0, %1;" : "=r"(u) : "f"(x));
    return __uint_as_float(u);
}
__device__ __forceinline__ void cp16s(uint32_t d, const float* s) {
    asm volatile("cp.async.cg.shared.global [%0], [%1], 16;" :: "r"(d), "l"(s));
}
__device__ __forceinline__ uint32_t smem_u32(const void* p) {
    uint32_t a;
    asm("{ .reg .u64 t; cvta.to.shared.u64 t, %1; cvt.u32.u64 %0, t; }" : "=r"(a) : "l"(p));
    return a;
}
__device__ __forceinline__ void mma_tf32(float* c, const uint32_t* a, uint32_t b0, uint32_t b1) {
    asm volatile(
        "mma.sync.aligned.m16n8k8.row.col.f32.tf32.tf32.f32 "
        "{%0,%1,%2,%3},{%4,%5,%6,%7},{%8,%9},{%0,%1,%2,%3};"
        : "+f"(c[0]), "+f"(c[1]), "+f"(c[2]), "+f"(c[3])
        : "r"(a[0]), "r"(a[1]), "r"(a[2]), "r"(a[3]), "r"(b0), "r"(b1));
}

// ============================================================================
// prep_w: fragment-layout weight panels, 3 Gauss batches per matrix.
// Layout: [panel(48)][batch(3)][kb(64)][1024 f4];  (panel,batch) chunk = 65536 f4.
// batch 0: Wr, 1: Wi, 2: Wr+Wi.  W is the raw 2048x6144 kernel (cols = 3 gates).
// ============================================================================
__global__ void prep_w(const float* __restrict__ rk,  const float* __restrict__ ik,
                       const float* __restrict__ rrk, const float* __restrict__ irk)
{
    const size_t PER = (size_t)48 * 3 * 65536;   // 9,437,184 f4 per matrix
    size_t fidx = (size_t)blockIdx.x * blockDim.x + threadIdx.x;
    const int mat = fidx >= PER;
    size_t loc = fidx - (size_t)mat * PER;

    const int pb    = (int)(loc >> 16);
    const int panel = pb / 3, batch = pb - panel * 3;
    const int rest  = (int)(loc & 65535);
    const int kb    = rest >> 10;
    const int x     = rest & 1023;
    const int q = x >> 5, lane = x & 31;
    const int ks = q >> 3, n16 = q & 7;
    const int grp = lane >> 2, tig = lane & 3;

    const int col = panel * 128 + n16 * 16 + grp;
    const int k   = kb * 32 + ks * 8 + tig;

    const float* Wr = mat ? rrk : rk;
    const float* Wi = mat ? irk : ik;
    const size_t o00 = (size_t)k * 6144 + col;
    const size_t o10 = o00 + (size_t)4 * 6144;

    float v0, v1, v2, v3;
    if (batch == 0) {
        v0 = Wr[o00]; v1 = Wr[o10]; v2 = Wr[o00 + 8]; v3 = Wr[o10 + 8];
    } else if (batch == 1) {
        v0 = Wi[o00]; v1 = Wi[o10]; v2 = Wi[o00 + 8]; v3 = Wi[o10 + 8];
    } else {
        v0 = Wr[o00] + Wi[o00];         v1 = Wr[o10] + Wi[o10];
        v2 = Wr[o00 + 8] + Wi[o00 + 8]; v3 = Wr[o10 + 8] + Wi[o10 + 8];
    }
    float* out = mat ? g_WR : g_WK;
    ((float4*)out)[loc] = make_float4(rndtf32(v0), rndtf32(v1), rndtf32(v2), rndtf32(v3));
}

// ============================================================================
// prep_a: operand fragments for inputs and h.
// Layout: [mp(8)][batch(3)][kb(64)][1024 f4].
// batch 0: A[:, :2048] (re), 1: A[:, 2048:] (im), 2: im - re.
// ============================================================================
__global__ void prep_a(const float* __restrict__ in0, const float* __restrict__ in1)
{
    const size_t PER = (size_t)8 * 3 * 65536;    // 1,572,864 f4 per source
    size_t fidx = (size_t)blockIdx.x * blockDim.x + threadIdx.x;
    const int src = fidx >= PER;
    size_t loc = fidx - (size_t)src * PER;

    const int mb = (int)(loc >> 16);
    const int mp = mb / 3, batch = mb - mp * 3;
    const int kb = (int)((loc >> 10) & 63);
    const int x  = (int)(loc & 1023);
    const int q = x >> 5, lane = x & 31;
    const int ks = q >> 3, m16 = q & 7;
    const int grp = lane >> 2, tig = lane & 3;

    const int m = mp * 128 + m16 * 16 + grp;
    const int k = kb * 32 + ks * 8 + tig;
    const float* A = src ? in1 : in0;
    const size_t r0 = (size_t)m * 4096, r1 = (size_t)(m + 8) * 4096;

    float a0, a1, a2, a3;
    if (batch == 0) {
        a0 = A[r0 + k];     a1 = A[r1 + k];
        a2 = A[r0 + k + 4]; a3 = A[r1 + k + 4];
    } else if (batch == 1) {
        a0 = A[r0 + 2048 + k];     a1 = A[r1 + 2048 + k];
        a2 = A[r0 + 2048 + k + 4]; a3 = A[r1 + 2048 + k + 4];
    } else {
        a0 = A[r0 + 2048 + k]     - A[r0 + k];
        a1 = A[r1 + 2048 + k]     - A[r1 + k];
        a2 = A[r0 + 2048 + k + 4] - A[r0 + k + 4];
        a3 = A[r1 + 2048 + k + 4] - A[r1 + k + 4];
    }
    float* out = src ? g_HF : g_AF;
    ((float4*)out)[loc] = make_float4(rndtf32(a0), rndtf32(a1), rndtf32(a2), rndtf32(a3));
}

// ============================================================================
// gemm_frag: 128x128 CTA tile, 4 warps of 64x64, K=2048, batch = blockIdx.z.
// ============================================================================
#define STAGES 3
#define STG_F (2 * TILE_F)
#define STG_BYTES (STG_F * 4)
#define GSMEM (STAGES * STG_BYTES)

__global__ __launch_bounds__(128, 2) void gemm_frag(
    const float* __restrict__ Ap, const float* __restrict__ Bp,
    float* __restrict__ C, int Nld, int pOff)
{
    extern __shared__ float sm[];
    const uint32_t sbase = smem_u32(sm);
    const int tid = threadIdx.x, wid = tid >> 5, lane = tid & 31;
    const int grp = lane >> 2, tig = lane & 3;
    const int mp = blockIdx.y, batch = blockIdx.z;
    const int panel = blockIdx.x + pOff;

    const float* At = Ap + (size_t)(mp * 3 + batch) * BSTRIDE;
    const float* Bt = Bp + (size_t)(panel * 3 + batch) * BSTRIDE;
    float* Cb = C + (size_t)batch * 1024 * Nld;

    const int wm16 = (wid & 1) * 4;
    const int wn16 = (wid >> 1) * 4;

    float acc[4][8][4];
#pragma unroll
    for (int a = 0; a < 4; a++)
#pragma unroll
        for (int b = 0; b < 8; b++)
#pragma unroll
            for (int c = 0; c < 4; c++) acc[a][b][c] = 0.0f;

    #define ISSUE(kb) do {                                                     \
        const uint32_t _st = sbase + ((kb) % STAGES) * STG_BYTES;              \
        const float* _sa = At + (size_t)(kb) * TILE_F;                         \
        const float* _sb = Bt + (size_t)(kb) * TILE_F;                         \
        _Pragma("unroll")                                                      \
        for (int _i = 0; _i < 8; _i++) {                                       \
            const int _o = (tid + _i * 128) * 4;                               \
            cp16s(_st + _o * 4, _sa + _o);                                     \
            cp16s(_st + 16384 + _o * 4, _sb + _o);                             \
        }                                                                      \
    } while (0)

    ISSUE(0);
    asm volatile("cp.async.commit_group;" ::: "memory");
    ISSUE(1);
    asm volatile("cp.async.commit_group;" ::: "memory");

    float4 af[2][4], bf[2][4];

    for (int kb = 0; kb < KITERS; ++kb) {
        asm volatile("cp.async.wait_group 1;" ::: "memory");
        __syncthreads();

        const float* As = sm + (kb % STAGES) * STG_F;
        const float* Bs = As + TILE_F;

#pragma unroll
        for (int t = 0; t < 4; ++t) {
            af[0][t] = *(const float4*)(As + ((wm16 + t) << 7) + (lane << 2));
            bf[0][t] = *(const float4*)(Bs + ((wn16 + t) << 7) + (lane << 2));
        }

#pragma unroll
        for (int ks = 0; ks < 4; ++ks) {
            const int cur = ks & 1;
            if (ks < 3) {
                const int nx = cur ^ 1, row = (ks + 1) * 8;
#pragma unroll
                for (int t = 0; t < 4; ++t) {
                    af[nx][t] = *(const float4*)(As + ((row + wm16 + t) << 7) + (lane << 2));
                    bf[nx][t] = *(const float4*)(Bs + ((row + wn16 + t) << 7) + (lane << 2));
                }
            }
#pragma unroll
            for (int tm = 0; tm < 4; ++tm) {
                const uint32_t* a = (const uint32_t*)&af[cur][tm];
#pragma unroll
                for (int p = 0; p < 4; ++p) {
                    const uint32_t* bu = (const uint32_t*)&bf[cur][p];
                    mma_tf32(acc[tm][p * 2],     a, bu[0], bu[1]);
                    mma_tf32(acc[tm][p * 2 + 1], a, bu[2], bu[3]);
                }
            }
        }

        if (kb + 2 < KITERS) ISSUE(kb + 2);
        asm volatile("cp.async.commit_group;" ::: "memory");
    }

#pragma unroll
    for (int tm = 0; tm < 4; ++tm) {
#pragma unroll
        for (int tn = 0; tn < 8; ++tn) {
            const int m0 = mp * 128 + (wid & 1) * 64 + tm * 16 + grp;
            const int n0 = blockIdx.x * 128 + (wid >> 1) * 64 + tn * 8 + tig * 2;
            *(float2*)&Cb[(size_t)m0 * Nld + n0]       = make_float2(acc[tm][tn][0], acc[tm][tn][1]);
            *(float2*)&Cb[(size_t)(m0 + 8) * Nld + n0] = make_float2(acc[tm][tn][2], acc[tm][tn][3]);
        }
    }
}

// ---------------------------------------------------------------- elementwise
__device__ __forceinline__ float hsig(float x) {
    return fminf(fmaxf(0.2f * x + 0.5f, 0.0f), 1.0f);
}

// z,r gates (Gauss combine) + RH fragments (3 batches).
__global__ void ew_zr(const float* __restrict__ P, const float* __restrict__ Q,
                      const float* __restrict__ h, const float* __restrict__ rb,
                      const float* __restrict__ ib, float* __restrict__ Z,
                      float* __restrict__ RHp)
{
    const int i = blockIdx.x * blockDim.x + threadIdx.x;  // 1024 x 512 f4
    const int m = i >> 9;
    const int jj = (i & 511) << 2;                        // j in [0,2048)

    const size_t PX = (size_t)1024 * 6144, QX = (size_t)1024 * 4096;
    const float* P1 = P + (size_t)m * 6144;
    const float* Q1 = Q + (size_t)m * 4096;

    // gate z (cols jj), gate r (cols 2048+jj)
    float4 p1z = *(const float4*)&P1[jj],        p2z = *(const float4*)&P1[PX + jj],
           p3z = *(const float4*)&P1[2*PX + jj];
    float4 p1r = *(const float4*)&P1[2048 + jj], p2r = *(const float4*)&P1[PX + 2048 + jj],
           p3r = *(const float4*)&P1[2*PX + 2048 + jj];
    float4 q1z = *(const float4*)&Q1[jj],        q2z = *(const float4*)&Q1[QX + jj],
           q3z = *(const float4*)&Q1[2*QX + jj];
    float4 q1r = *(const float4*)&Q1[2048 + jj], q2r = *(const float4*)&Q1[QX + 2048 + jj],
           q3r = *(const float4*)&Q1[2*QX + 2048 + jj];

    float4 hre = *(const float4*)&h[(size_t)m * 4096 + jj];
    float4 him = *(const float4*)&h[(size_t)m * 4096 + 2048 + jj];
    float4 bzr = *(const float4*)&rb[jj],        bzi = *(const float4*)&ib[jj];
    float4 brr = *(const float4*)&rb[2048 + jj], bri = *(const float4*)&ib[2048 + jj];

    float zre[4], zim[4], rhre[4], rhim[4], rhd[4];
#pragma unroll
    for (int c = 0; c < 4; c++) {
        float P1z = (&p1z.x)[c], P2z = (&p2z.x)[c], P3z = (&p3z.x)[c];
        float P1r = (&p1r.x)[c], P2r = (&p2r.x)[c], P3r = (&p3r.x)[c];
        float Q1z = (&q1z.x)[c], Q2z = (&q2z.x)[c], Q3z = (&q3z.x)[c];
        float Q1r = (&q1r.x)[c], Q2r = (&q2r.x)[c], Q3r = (&q3r.x)[c];
        zre[c] = hsig(P1z + P2z + (&bzr.x)[c] + Q1z + Q2z);
        zim[c] = hsig(P3z + P1z - P2z + (&bzi.x)[c] + Q3z + Q1z - Q2z);
        float rre = hsig(P1r + P2r + (&brr.x)[c] + Q1r + Q2r);
        float rim = hsig(P3r + P1r - P2r + (&bri.x)[c] + Q3r + Q1r - Q2r);
        float vre = rre * (&hre.x)[c];
        float vim = rim * (&him.x)[c];
        rhre[c] = rndtf32(vre);
        rhim[c] = rndtf32(vim);
        rhd[c]  = rndtf32(vim - vre);
    }

    *(float4*)&Z[(size_t)m * 4096 + jj]        = make_float4(zre[0], zre[1], zre[2], zre[3]);
    *(float4*)&Z[(size_t)m * 4096 + 2048 + jj] = make_float4(zim[0], zim[1], zim[2], zim[3]);

    // fragment scatter: RH batches 0(re),1(im),2(im-re)
    const int mp = m >> 7, m16 = (m >> 4) & 7;
    const int grpm = m & 7, hi = (m >> 3) & 1;
    const int kb = jj >> 5, ks = (jj >> 3) & 3, kh = (jj >> 2) & 1;
    size_t base = ((size_t)(mp * 3) * KITERS + kb) * TILE_F
                + ((ks * 8 + m16) << 7) + (grpm << 4) + hi + (kh << 1);
#pragma unroll
    for (int c = 0; c < 4; c++) {
        RHp[base + 4 * c]               = rhre[c];
        RHp[base + BSTRIDE + 4 * c]     = rhim[c];
        RHp[base + 2 * BSTRIDE + 4 * c] = rhd[c];
    }
}

// final blend (Gauss combine for x_h and HH)
__global__ void ew_out(const float* __restrict__ P, const float* __restrict__ R,
                       const float* __restrict__ h, const float* __restrict__ rb,
                       const float* __restrict__ ib, const float* __restrict__ Z,
                       float* __restrict__ out)
{
    const int i = blockIdx.x * blockDim.x + threadIdx.x;
    const int m = i >> 9;
    const int jj = (i & 511) << 2;

    const size_t PX = (size_t)1024 * 6144, RX = (size_t)1024 * 2048;
    const float* P1 = P + (size_t)m * 6144;
    const float* R1 = R + (size_t)m * 2048;

    float4 p1 = *(const float4*)&P1[4096 + jj],      p2 = *(const float4*)&P1[PX + 4096 + jj],
           p3 = *(const float4*)&P1[2*PX + 4096 + jj];
    float4 r1 = *(const float4*)&R1[jj], r2 = *(const float4*)&R1[RX + jj],
           r3 = *(const float4*)&R1[2*RX + jj];

    float4 hre = *(const float4*)&h[(size_t)m * 4096 + jj];
    float4 him = *(const float4*)&h[(size_t)m * 4096 + 2048 + jj];
    float4 zre = *(const float4*)&Z[(size_t)m * 4096 + jj];
    float4 zim = *(const float4*)&Z[(size_t)m * 4096 + 2048 + jj];
    float4 bhr = *(const float4*)&rb[4096 + jj], bhi = *(const float4*)&ib[4096 + jj];

    float ore[4], oim[4];
#pragma unroll
    for (int c = 0; c < 4; c++) {
        float A1 = (&p1.x)[c], A2 = (&p2.x)[c], A3 = (&p3.x)[c];
        float B1 = (&r1.x)[c], B2 = (&r2.x)[c], B3 = (&r3.x)[c];
        float xre = A1 + A2 + (&bhr.x)[c] + B1 + B2;
        float xim = A3 + A1 - A2 + (&bhi.x)[c] + B3 + B1 - B2;
        float tre = tanhf(xre), tim = tanhf(xim);
        float Zr = (&zre.x)[c], Zi = (&zim.x)[c];
        ore[c] = Zr * (&hre.x)[c] + (1.0f - Zr) * tre;
        oim[c] = Zi * (&him.x)[c] + (1.0f - Zi) * tim;
    }
    *(float4*)&out[(size_t)m * 4096 + jj]        = make_float4(ore[0], ore[1], ore[2], ore[3]);
    *(float4*)&out[(size_t)m * 4096 + 2048 + jj] = make_float4(oim[0], oim[1], oim[2], oim[3]);
}

// --------------------------------------------------------------------- launch
extern "C" void kernel_launch(void* const* d_in, const int* in_sizes, int n_in,
                              void* d_out, int out_size)
{
    const float* inputs = (const float*)d_in[0];
    const float* h_tm1  = (const float*)d_in[1];
    const float* rk     = (const float*)d_in[2];
    const float* ik     = (const float*)d_in[3];
    const float* rrk    = (const float*)d_in[4];
    const float* irk    = (const float*)d_in[5];
    const float* rb     = (const float*)d_in[6];
    const float* ib     = (const float*)d_in[7];
    float* out = (float*)d_out;

    float *pWK, *pWR, *pAF, *pHF, *pRHF, *pP, *pQ, *pR, *pZ;
    cudaGetSymbolAddress((void**)&pWK,  g_WK);
    cudaGetSymbolAddress((void**)&pWR,  g_WR);
    cudaGetSymbolAddress((void**)&pAF,  g_AF);
    cudaGetSymbolAddress((void**)&pHF,  g_HF);
    cudaGetSymbolAddress((void**)&pRHF, g_RHF);
    cudaGetSymbolAddress((void**)&pP,   g_P);
    cudaGetSymbolAddress((void**)&pQ,   g_Q);
    cudaGetSymbolAddress((void**)&pR,   g_R);
    cudaGetSymbolAddress((void**)&pZ,   g_Z);

    cudaFuncSetAttribute(gemm_frag, cudaFuncAttributeMaxDynamicSharedMemorySize, GSMEM);

    // materialize fragment-layout operands (Gauss batches)
    prep_w<<<73728, 256>>>(rk, ik, rrk, irk);
    prep_a<<<12288, 256>>>(inputs, h_tm1);

    // P = {Ar,Ai,Ai-Ar} @ {Kr,Ki,Kr+Ki}   (N = 6144, 3 batches)
    gemm_frag<<<dim3(48, 8, 3), 128, GSMEM>>>(pAF, pWK, pP, 6144, 0);
    // Q = h-batches @ R-batches, gates z,r (N = 4096)
    gemm_frag<<<dim3(32, 8, 3), 128, GSMEM>>>(pHF, pWR, pQ, 4096, 0);
    // gates + RH fragments
    ew_zr<<<2048, 256>>>(pP, pQ, h_tm1, rb, ib, pZ, pRHF);
    // R = RH-batches @ R-batches, gate h (N = 2048, panels 32..47)
    gemm_frag<<<dim3(16, 8, 3), 128, GSMEM>>>(pRHF, pWR, pR, 2048, 32);
    // out
    ew_out<<<2048, 256>>>(pP, pR, h_tm1, rb, ib, pZ, out);
}

// round 8
// speedup vs baseline: 2.0823x; 1.0243x over previous
#include <cuda_runtime.h>
#include <cstdint>
#include <cmath>

// ============================================================================
// CGRU cell, B=1024, UNITS=2048 — Gauss 3-mult complex GEMM, TF32 mma.sync.
//   Re(A@conj(W)) = P1 + P2,  Im = P3 + P1 - P2
//   P1 = Ar@Wr, P2 = Ai@Wi, P3 = (Ai-Ar)@(Wr+Wi)   (each K=2048)
// v3: smem-staged coalesced prep kernels; split-K x2 for the final GEMM.
// ============================================================================

#define TILE_F 4096      // floats per 128x32 tile
#define KITERS 64        // 2048 / 32
#define BSTRIDE ((size_t)KITERS * TILE_F)   // floats per (unit,batch)

// ------------------------------ scratch (device globals, allocation-free) --
__device__ float g_WK [(size_t)48 * 3 * BSTRIDE]; // input-kernel fragments (151MB)
__device__ float g_WR [(size_t)48 * 3 * BSTRIDE]; // recurrent fragments    (151MB)
__device__ float g_AF [(size_t)8  * 3 * BSTRIDE]; // inputs' (25MB)
__device__ float g_HF [(size_t)8  * 3 * BSTRIDE]; // h'      (25MB)
__device__ float g_RHF[(size_t)8  * 3 * BSTRIDE]; // (r*h)'  (25MB)
__device__ float g_P  [(size_t)3 * 1024 * 6144];  // input-GEMM Ps (75MB)
__device__ float g_Q  [(size_t)3 * 1024 * 4096];  // z,r recurrent Ps
__device__ float g_R  [(size_t)6 * 1024 * 2048];  // h recurrent Ps (split-K x2)
__device__ float g_Z  [(size_t)1024 * 4096];

// ----------------------------------------------------------------- helpers --
__device__ __forceinline__ float rndtf32(float x) {
    uint32_t u;
    asm("cvt.rna.tf32.f32 %0, %1;" : "=r"(u) : "f"(x));
    return __uint_as_float(u);
}
__device__ __forceinline__ void cp16s(uint32_t d, const float* s) {
    asm volatile("cp.async.cg.shared.global [%0], [%1], 16;" :: "r"(d), "l"(s));
}
__device__ __forceinline__ uint32_t smem_u32(const void* p) {
    uint32_t a;
    asm("{ .reg .u64 t; cvta.to.shared.u64 t, %1; cvt.u32.u64 %0, t; }" : "=r"(a) : "l"(p));
    return a;
}
__device__ __forceinline__ void mma_tf32(float* c, const uint32_t* a, uint32_t b0, uint32_t b1) {
    asm volatile(
        "mma.sync.aligned.m16n8k8.row.col.f32.tf32.tf32.f32 "
        "{%0,%1,%2,%3},{%4,%5,%6,%7},{%8,%9},{%0,%1,%2,%3};"
        : "+f"(c[0]), "+f"(c[1]), "+f"(c[2]), "+f"(c[3])
        : "r"(a[0]), "r"(a[1]), "r"(a[2]), "r"(a[3]), "r"(b0), "r"(b1));
}

// ============================================================================
// prep_w v2: smem-staged, fully coalesced.
// Block = one (matrix, panel, kb): loads Wr/Wi 32x128 sub-tiles coalesced,
// emits 3 Gauss batch fragment tiles (1024 f4 each) with coalesced stores.
// Fragment layout: [panel(48)][batch(3)][kb(64)][1024 f4].
// ============================================================================
#define PWS 136   // smem row stride (floats): conflict-free for (grp,tig) LDS

__global__ __launch_bounds__(256) void prep_w(
    const float* __restrict__ rk,  const float* __restrict__ ik,
    const float* __restrict__ rrk, const float* __restrict__ irk)
{
    __shared__ float sr[32 * PWS], si[32 * PWS];
    const int tid = threadIdx.x;
    const int b = blockIdx.x;                 // 0..6143
    const int mat = b >= 3072;
    const int rem = b - mat * 3072;
    const int panel = rem >> 6;
    const int kb = rem & 63;

    const float* Wr = mat ? rrk : rk;
    const float* Wi = mat ? irk : ik;
    const size_t gbase = (size_t)(kb * 32) * 6144 + panel * 128;

#pragma unroll
    for (int t = 0; t < 4; t++) {
        const int idx = tid + t * 256;        // 1024 f4 per tile
        const int row = idx >> 5, c4 = idx & 31;
        const size_t ga = gbase + (size_t)row * 6144 + c4 * 4;
        *(float4*)&sr[row * PWS + c4 * 4] = *(const float4*)&Wr[ga];
        *(float4*)&si[row * PWS + c4 * 4] = *(const float4*)&Wi[ga];
    }
    __syncthreads();

    float4* O = (float4*)(mat ? g_WR : g_WK);
    const size_t obase = ((size_t)(panel * 3) * 64 + kb) * 1024;

#pragma unroll
    for (int t = 0; t < 4; t++) {
        const int x = tid + t * 256;
        const int q = x >> 5, lane = x & 31;
        const int ks = q >> 3, n16 = q & 7;
        const int grp = lane >> 2, tig = lane & 3;
        const int kl = ks * 8 + tig;
        const int cl = n16 * 16 + grp;

        float wr0 = sr[kl * PWS + cl],       wr1 = sr[(kl + 4) * PWS + cl];
        float wr2 = sr[kl * PWS + cl + 8],   wr3 = sr[(kl + 4) * PWS + cl + 8];
        float wi0 = si[kl * PWS + cl],       wi1 = si[(kl + 4) * PWS + cl];
        float wi2 = si[kl * PWS + cl + 8],   wi3 = si[(kl + 4) * PWS + cl + 8];

        O[obase + x] = make_float4(rndtf32(wr0), rndtf32(wr1), rndtf32(wr2), rndtf32(wr3));
        O[obase + 65536 + x] = make_float4(rndtf32(wi0), rndtf32(wi1), rndtf32(wi2), rndtf32(wi3));
        O[obase + 131072 + x] = make_float4(rndtf32(wr0 + wi0), rndtf32(wr1 + wi1),
                                            rndtf32(wr2 + wi2), rndtf32(wr3 + wi3));
    }
}

// ============================================================================
// prep_a v2: smem-staged. Block = one (source, mp, kb): loads 128x32 re/im
// column slabs coalesced, emits 3 batch fragment tiles.
// Layout: [mp(8)][batch(3)][kb(64)][1024 f4].
// ============================================================================
#define PAS 36    // smem row stride (floats): conflict-free for (grp,tig) LDS

__global__ __launch_bounds__(256) void prep_a(
    const float* __restrict__ in0, const float* __restrict__ in1)
{
    __shared__ float s0[128 * PAS], s1[128 * PAS];
    const int tid = threadIdx.x;
    const int b = blockIdx.x;                 // 0..1023
    const int src = b >> 9;
    const int rem = b & 511;
    const int mp = rem >> 6;
    const int kb = rem & 63;

    const float* A = src ? in1 : in0;

#pragma unroll
    for (int t = 0; t < 8; t++) {
        const int idx = tid + t * 256;        // 2048 f4: half(2) x row(128) x c4(8)
        const int half = idx >> 10;
        const int i2 = idx & 1023;
        const int row = i2 >> 3, c4 = i2 & 7;
        const float4 v = *(const float4*)&A[(size_t)(mp * 128 + row) * 4096
                                            + half * 2048 + kb * 32 + c4 * 4];
        float* s = half ? s1 : s0;
        *(float4*)&s[row * PAS + c4 * 4] = v;
    }
    __syncthreads();

    float4* O = (float4*)(src ? g_HF : g_AF);
    const size_t obase = ((size_t)(mp * 3) * 64 + kb) * 1024;

#pragma unroll
    for (int t = 0; t < 4; t++) {
        const int x = tid + t * 256;
        const int q = x >> 5, lane = x & 31;
        const int ks = q >> 3, m16 = q & 7;
        const int grp = lane >> 2, tig = lane & 3;
        const int ml = m16 * 16 + grp;
        const int kl = ks * 8 + tig;

        float r0 = s0[ml * PAS + kl],           r1 = s0[(ml + 8) * PAS + kl];
        float r2 = s0[ml * PAS + kl + 4],       r3 = s0[(ml + 8) * PAS + kl + 4];
        float i0v = s1[ml * PAS + kl],          i1v = s1[(ml + 8) * PAS + kl];
        float i2v = s1[ml * PAS + kl + 4],      i3v = s1[(ml + 8) * PAS + kl + 4];

        O[obase + x] = make_float4(rndtf32(r0), rndtf32(r1), rndtf32(r2), rndtf32(r3));
        O[obase + 65536 + x] = make_float4(rndtf32(i0v), rndtf32(i1v), rndtf32(i2v), rndtf32(i3v));
        O[obase + 131072 + x] = make_float4(rndtf32(i0v - r0), rndtf32(i1v - r1),
                                            rndtf32(i2v - r2), rndtf32(i3v - r3));
    }
}

// ============================================================================
// gemm_frag: 128x128 CTA tile, 4 warps of 64x64, runtime K-iter count,
// batch/split-K via blockIdx.z (z = half*3 + batch, kOff = half*kIters).
// ============================================================================
#define STAGES 3
#define STG_F (2 * TILE_F)
#define STG_BYTES (STG_F * 4)
#define GSMEM (STAGES * STG_BYTES)

__global__ __launch_bounds__(128, 2) void gemm_frag(
    const float* __restrict__ Ap, const float* __restrict__ Bp,
    float* __restrict__ C, int Nld, int pOff, int kIters)
{
    extern __shared__ float sm[];
    const uint32_t sbase = smem_u32(sm);
    const int tid = threadIdx.x, wid = tid >> 5, lane = tid & 31;
    const int grp = lane >> 2, tig = lane & 3;
    const int mp = blockIdx.y;
    const int z = blockIdx.z;
    const int batch = z % 3, half = z / 3;
    const int panel = blockIdx.x + pOff;
    const int kO = half * kIters;

    const float* At = Ap + (size_t)(mp * 3 + batch) * BSTRIDE + (size_t)kO * TILE_F;
    const float* Bt = Bp + (size_t)(panel * 3 + batch) * BSTRIDE + (size_t)kO * TILE_F;
    float* Cb = C + (size_t)z * 1024 * Nld;

    const int wm16 = (wid & 1) * 4;
    const int wn16 = (wid >> 1) * 4;

    float acc[4][8][4];
#pragma unroll
    for (int a = 0; a < 4; a++)
#pragma unroll
        for (int b = 0; b < 8; b++)
#pragma unroll
            for (int c = 0; c < 4; c++) acc[a][b][c] = 0.0f;

    #define ISSUE(kb) do {                                                     \
        const uint32_t _st = sbase + ((kb) % STAGES) * STG_BYTES;              \
        const float* _sa = At + (size_t)(kb) * TILE_F;                         \
        const float* _sb = Bt + (size_t)(kb) * TILE_F;                         \
        _Pragma("unroll")                                                      \
        for (int _i = 0; _i < 8; _i++) {                                       \
            const int _o = (tid + _i * 128) * 4;                               \
            cp16s(_st + _o * 4, _sa + _o);                                     \
            cp16s(_st + 16384 + _o * 4, _sb + _o);                             \
        }                                                                      \
    } while (0)

    ISSUE(0);
    asm volatile("cp.async.commit_group;" ::: "memory");
    ISSUE(1);
    asm volatile("cp.async.commit_group;" ::: "memory");

    float4 af[2][4], bf[2][4];

    for (int kb = 0; kb < kIters; ++kb) {
        asm volatile("cp.async.wait_group 1;" ::: "memory");
        __syncthreads();

        const float* As = sm + (kb % STAGES) * STG_F;
        const float* Bs = As + TILE_F;

#pragma unroll
        for (int t = 0; t < 4; ++t) {
            af[0][t] = *(const float4*)(As + ((wm16 + t) << 7) + (lane << 2));
            bf[0][t] = *(const float4*)(Bs + ((wn16 + t) << 7) + (lane << 2));
        }

#pragma unroll
        for (int ks = 0; ks < 4; ++ks) {
            const int cur = ks & 1;
            if (ks < 3) {
                const int nx = cur ^ 1, row = (ks + 1) * 8;
#pragma unroll
                for (int t = 0; t < 4; ++t) {
                    af[nx][t] = *(const float4*)(As + ((row + wm16 + t) << 7) + (lane << 2));
                    bf[nx][t] = *(const float4*)(Bs + ((row + wn16 + t) << 7) + (lane << 2));
                }
            }
#pragma unroll
            for (int tm = 0; tm < 4; ++tm) {
                const uint32_t* a = (const uint32_t*)&af[cur][tm];
#pragma unroll
                for (int p = 0; p < 4; ++p) {
                    const uint32_t* bu = (const uint32_t*)&bf[cur][p];
                    mma_tf32(acc[tm][p * 2],     a, bu[0], bu[1]);
                    mma_tf32(acc[tm][p * 2 + 1], a, bu[2], bu[3]);
                }
            }
        }

        if (kb + 2 < kIters) ISSUE(kb + 2);
        asm volatile("cp.async.commit_group;" ::: "memory");
    }

#pragma unroll
    for (int tm = 0; tm < 4; ++tm) {
#pragma unroll
        for (int tn = 0; tn < 8; ++tn) {
            const int m0 = mp * 128 + (wid & 1) * 64 + tm * 16 + grp;
            const int n0 = blockIdx.x * 128 + (wid >> 1) * 64 + tn * 8 + tig * 2;
            *(float2*)&Cb[(size_t)m0 * Nld + n0]       = make_float2(acc[tm][tn][0], acc[tm][tn][1]);
            *(float2*)&Cb[(size_t)(m0 + 8) * Nld + n0] = make_float2(acc[tm][tn][2], acc[tm][tn][3]);
        }
    }
}

// ---------------------------------------------------------------- elementwise
__device__ __forceinline__ float hsig(float x) {
    return fminf(fmaxf(0.2f * x + 0.5f, 0.0f), 1.0f);
}

// z,r gates (Gauss combine) + RH fragments (3 batches).
__global__ void ew_zr(const float* __restrict__ P, const float* __restrict__ Q,
                      const float* __restrict__ h, const float* __restrict__ rb,
                      const float* __restrict__ ib, float* __restrict__ Z,
                      float* __restrict__ RHp)
{
    const int i = blockIdx.x * blockDim.x + threadIdx.x;  // 1024 x 512 f4
    const int m = i >> 9;
    const int jj = (i & 511) << 2;                        // j in [0,2048)

    const size_t PX = (size_t)1024 * 6144, QX = (size_t)1024 * 4096;
    const float* P1 = P + (size_t)m * 6144;
    const float* Q1 = Q + (size_t)m * 4096;

    float4 p1z = *(const float4*)&P1[jj],        p2z = *(const float4*)&P1[PX + jj],
           p3z = *(const float4*)&P1[2*PX + jj];
    float4 p1r = *(const float4*)&P1[2048 + jj], p2r = *(const float4*)&P1[PX + 2048 + jj],
           p3r = *(const float4*)&P1[2*PX + 2048 + jj];
    float4 q1z = *(const float4*)&Q1[jj],        q2z = *(const float4*)&Q1[QX + jj],
           q3z = *(const float4*)&Q1[2*QX + jj];
    float4 q1r = *(const float4*)&Q1[2048 + jj], q2r = *(const float4*)&Q1[QX + 2048 + jj],
           q3r = *(const float4*)&Q1[2*QX + 2048 + jj];

    float4 hre = *(const float4*)&h[(size_t)m * 4096 + jj];
    float4 him = *(const float4*)&h[(size_t)m * 4096 + 2048 + jj];
    float4 bzr = *(const float4*)&rb[jj],        bzi = *(const float4*)&ib[jj];
    float4 brr = *(const float4*)&rb[2048 + jj], bri = *(const float4*)&ib[2048 + jj];

    float zre[4], zim[4], rhre[4], rhim[4], rhd[4];
#pragma unroll
    for (int c = 0; c < 4; c++) {
        float P1z = (&p1z.x)[c], P2z = (&p2z.x)[c], P3z = (&p3z.x)[c];
        float P1r = (&p1r.x)[c], P2r = (&p2r.x)[c], P3r = (&p3r.x)[c];
        float Q1z = (&q1z.x)[c], Q2z = (&q2z.x)[c], Q3z = (&q3z.x)[c];
        float Q1r = (&q1r.x)[c], Q2r = (&q2r.x)[c], Q3r = (&q3r.x)[c];
        zre[c] = hsig(P1z + P2z + (&bzr.x)[c] + Q1z + Q2z);
        zim[c] = hsig(P3z + P1z - P2z + (&bzi.x)[c] + Q3z + Q1z - Q2z);
        float rre = hsig(P1r + P2r + (&brr.x)[c] + Q1r + Q2r);
        float rim = hsig(P3r + P1r - P2r + (&bri.x)[c] + Q3r + Q1r - Q2r);
        float vre = rre * (&hre.x)[c];
        float vim = rim * (&him.x)[c];
        rhre[c] = rndtf32(vre);
        rhim[c] = rndtf32(vim);
        rhd[c]  = rndtf32(vim - vre);
    }

    *(float4*)&Z[(size_t)m * 4096 + jj]        = make_float4(zre[0], zre[1], zre[2], zre[3]);
    *(float4*)&Z[(size_t)m * 4096 + 2048 + jj] = make_float4(zim[0], zim[1], zim[2], zim[3]);

    const int mp = m >> 7, m16 = (m >> 4) & 7;
    const int grpm = m & 7, hi = (m >> 3) & 1;
    const int kb = jj >> 5, ks = (jj >> 3) & 3, kh = (jj >> 2) & 1;
    size_t base = ((size_t)(mp * 3) * KITERS + kb) * TILE_F
                + ((ks * 8 + m16) << 7) + (grpm << 4) + hi + (kh << 1);
#pragma unroll
    for (int c = 0; c < 4; c++) {
        RHp[base + 4 * c]               = rhre[c];
        RHp[base + BSTRIDE + 4 * c]     = rhim[c];
        RHp[base + 2 * BSTRIDE + 4 * c] = rhd[c];
    }
}

// final blend (Gauss combine, split-K halves summed here)
__global__ void ew_out(const float* __restrict__ P, const float* __restrict__ R,
                       const float* __restrict__ h, const float* __restrict__ rb,
                       const float* __restrict__ ib, const float* __restrict__ Z,
                       float* __restrict__ out)
{
    const int i = blockIdx.x * blockDim.x + threadIdx.x;
    const int m = i >> 9;
    const int jj = (i & 511) << 2;

    const size_t PX = (size_t)1024 * 6144, RX = (size_t)1024 * 2048;
    const float* P1 = P + (size_t)m * 6144;
    const float* R1 = R + (size_t)m * 2048;

    float4 p1 = *(const float4*)&P1[4096 + jj],      p2 = *(const float4*)&P1[PX + 4096 + jj],
           p3 = *(const float4*)&P1[2*PX + 4096 + jj];
    float4 r1a = *(const float4*)&R1[jj],       r1b = *(const float4*)&R1[3*RX + jj];
    float4 r2a = *(const float4*)&R1[RX + jj],  r2b = *(const float4*)&R1[4*RX + jj];
    float4 r3a = *(const float4*)&R1[2*RX + jj],r3b = *(const float4*)&R1[5*RX + jj];

    float4 hre = *(const float4*)&h[(size_t)m * 4096 + jj];
    float4 him = *(const float4*)&h[(size_t)m * 4096 + 2048 + jj];
    float4 zre = *(const float4*)&Z[(size_t)m * 4096 + jj];
    float4 zim = *(const float4*)&Z[(size_t)m * 4096 + 2048 + jj];
    float4 bhr = *(const float4*)&rb[4096 + jj], bhi = *(const float4*)&ib[4096 + jj];

    float ore[4], oim[4];
#pragma unroll
    for (int c = 0; c < 4; c++) {
        float A1 = (&p1.x)[c], A2 = (&p2.x)[c], A3 = (&p3.x)[c];
        float B1 = (&r1a.x)[c] + (&r1b.x)[c];
        float B2 = (&r2a.x)[c] + (&r2b.x)[c];
        float B3 = (&r3a.x)[c] + (&r3b.x)[c];
        float xre = A1 + A2 + (&bhr.x)[c] + B1 + B2;
        float xim = A3 + A1 - A2 + (&bhi.x)[c] + B3 + B1 - B2;
        float tre = tanhf(xre), tim = tanhf(xim);
        float Zr = (&zre.x)[c], Zi = (&zim.x)[c];
        ore[c] = Zr * (&hre.x)[c] + (1.0f - Zr) * tre;
        oim[c] = Zi * (&him.x)[c] + (1.0f - Zi) * tim;
    }
    *(float4*)&out[(size_t)m * 4096 + jj]        = make_float4(ore[0], ore[1], ore[2], ore[3]);
    *(float4*)&out[(size_t)m * 4096 + 2048 + jj] = make_float4(oim[0], oim[1], oim[2], oim[3]);
}

// --------------------------------------------------------------------- launch
extern "C" void kernel_launch(void* const* d_in, const int* in_sizes, int n_in,
                              void* d_out, int out_size)
{
    const float* inputs = (const float*)d_in[0];
    const float* h_tm1  = (const float*)d_in[1];
    const float* rk     = (const float*)d_in[2];
    const float* ik     = (const float*)d_in[3];
    const float* rrk    = (const float*)d_in[4];
    const float* irk    = (const float*)d_in[5];
    const float* rb     = (const float*)d_in[6];
    const float* ib     = (const float*)d_in[7];
    float* out = (float*)d_out;

    float *pWK, *pWR, *pAF, *pHF, *pRHF, *pP, *pQ, *pR, *pZ;
    cudaGetSymbolAddress((void**)&pWK,  g_WK);
    cudaGetSymbolAddress((void**)&pWR,  g_WR);
    cudaGetSymbolAddress((void**)&pAF,  g_AF);
    cudaGetSymbolAddress((void**)&pHF,  g_HF);
    cudaGetSymbolAddress((void**)&pRHF, g_RHF);
    cudaGetSymbolAddress((void**)&pP,   g_P);
    cudaGetSymbolAddress((void**)&pQ,   g_Q);
    cudaGetSymbolAddress((void**)&pR,   g_R);
    cudaGetSymbolAddress((void**)&pZ,   g_Z);

    cudaFuncSetAttribute(gemm_frag, cudaFuncAttributeMaxDynamicSharedMemorySize, GSMEM);

    // materialize fragment-layout operands (coalesced, smem-staged)
    prep_w<<<6144, 256>>>(rk, ik, rrk, irk);
    prep_a<<<1024, 256>>>(inputs, h_tm1);

    // P = {Ar,Ai,Ai-Ar} @ {Kr,Ki,Kr+Ki}   (N = 6144, 3 batches, K = 2048)
    gemm_frag<<<dim3(48, 8, 3), 128, GSMEM>>>(pAF, pWK, pP, 6144, 0, KITERS);
    // Q = h-batches @ R-batches, gates z,r (N = 4096, K = 2048)
    gemm_frag<<<dim3(32, 8, 3), 128, GSMEM>>>(pHF, pWR, pQ, 4096, 0, KITERS);
    // gates + RH fragments
    ew_zr<<<2048, 256>>>(pP, pQ, h_tm1, rb, ib, pZ, pRHF);
    // R = RH-batches @ R-batches, gate h (N = 2048, panels 32..47, split-K x2)
    gemm_frag<<<dim3(16, 8, 6), 128, GSMEM>>>(pRHF, pWR, pR, 2048, 32, 32);
    // out
    ew_out<<<2048, 256>>>(pP, pR, h_tm1, rb, ib, pZ, out);
}

// round 9
// speedup vs baseline: 3.8270x; 1.8378x over previous
#include <cuda_runtime.h>
#include <cuda_fp16.h>
#include <cstdint>
#include <cmath>

// ============================================================================
// CGRU cell, B=1024, UNITS=2048 — Gauss 3-mult complex GEMM, FP16 mma.sync.
//   Re(A@conj(W)) = P1 + P2,  Im = P3 + P1 - P2
//   P1 = Ar@Wr, P2 = Ai@Wi, P3 = (Ai-Ar)@(Wr+Wi)   (each K=2048)
// Operands quantized to fp16 (same 10-bit mantissa as tf32), fp32 accumulate.
// m16n8k16 fragment layout materialized by prep kernels; GEMM inner loop is
// pure LDS.128 + HMMA.16816. 128x128 CTA tile, 4 warps of 64x64, BK=32.
// ============================================================================

#define KITERS 64                       // 2048 / 32
#define TU4 512                         // uint4 per 128x32 (or 32x128) fp16 tile
#define BSTR ((size_t)KITERS * TU4)     // uint4 per (unit,batch) fragment panel

// ------------------------------ scratch (device globals, allocation-free) --
__device__ uint4 g_WK [(size_t)48 * 3 * BSTR];  // input-kernel fragments (75MB)
__device__ uint4 g_WR [(size_t)48 * 3 * BSTR];  // recurrent fragments    (75MB)
__device__ uint4 g_AF [(size_t)8  * 3 * BSTR];  // inputs' (12.6MB)
__device__ uint4 g_HF [(size_t)8  * 3 * BSTR];  // h'      (12.6MB)
__device__ uint4 g_RHF[(size_t)8  * 3 * BSTR];  // (r*h)'  (12.6MB)
__device__ float g_P  [(size_t)3 * 1024 * 6144]; // input-GEMM Ps (75MB)
__device__ float g_Q  [(size_t)3 * 1024 * 4096]; // z,r recurrent Ps
__device__ float g_R  [(size_t)6 * 1024 * 2048]; // h recurrent Ps (split-K x2)
__device__ float g_Z  [(size_t)1024 * 4096];

// ----------------------------------------------------------------- helpers --
__device__ __forceinline__ void cp16s(uint32_t d, const void* s) {
    asm volatile("cp.async.cg.shared.global [%0], [%1], 16;" :: "r"(d), "l"(s));
}
__device__ __forceinline__ uint32_t smem_u32(const void* p) {
    uint32_t a;
    asm("{ .reg .u64 t; cvta.to.shared.u64 t, %1; cvt.u32.u64 %0, t; }" : "=r"(a) : "l"(p));
    return a;
}
__device__ __forceinline__ void mma_f16(float* c, const uint32_t* a, uint32_t b0, uint32_t b1) {
    asm volatile(
        "mma.sync.aligned.m16n8k16.row.col.f32.f16.f16.f32 "
        "{%0,%1,%2,%3},{%4,%5,%6,%7},{%8,%9},{%0,%1,%2,%3};"
        : "+f"(c[0]), "+f"(c[1]), "+f"(c[2]), "+f"(c[3])
        : "r"(a[0]), "r"(a[1]), "r"(a[2]), "r"(a[3]), "r"(b0), "r"(b1));
}
__device__ __forceinline__ uint32_t packh2(float a, float b) {
    __half2 h = __floats2half2_rn(a, b);
    return *(uint32_t*)&h;
}

// ============================================================================
// prep_w: fp16 B-fragment panels, 3 Gauss batches per matrix.
// B-fragment uint4 (m16n8k16, col-major B), index x in [0,512):
//   n16 = x>>6, k16 = (x>>5)&1, lane = x&31, grp = lane>>2, tig = lane&3
//   c = n16*16+grp, k0 = k16*16+tig*2
//   halves = {W[k0,c],W[k0+1,c], W[k0+8,c],W[k0+9,c],
//             W[k0,c+8],W[k0+1,c+8], W[k0+8,c+8],W[k0+9,c+8]}
// Layout: [panel(48)][batch(3)][kb(64)][512 u4]; batch 0=Wr, 1=Wi, 2=Wr+Wi.
// ============================================================================
#define PWS 136

__global__ __launch_bounds__(256) void prep_w(
    const float* __restrict__ rk,  const float* __restrict__ ik,
    const float* __restrict__ rrk, const float* __restrict__ irk)
{
    __shared__ float sr[32 * PWS], si[32 * PWS];
    const int tid = threadIdx.x;
    const int b = blockIdx.x;                 // 0..6143
    const int mat = b >= 3072;
    const int rem = b - mat * 3072;
    const int panel = rem >> 6;
    const int kb = rem & 63;

    const float* Wr = mat ? rrk : rk;
    const float* Wi = mat ? irk : ik;
    const size_t gbase = (size_t)(kb * 32) * 6144 + panel * 128;

#pragma unroll
    for (int t = 0; t < 4; t++) {
        const int idx = tid + t * 256;        // 1024 f4 per tile
        const int row = idx >> 5, c4 = idx & 31;
        const size_t ga = gbase + (size_t)row * 6144 + c4 * 4;
        *(float4*)&sr[row * PWS + c4 * 4] = *(const float4*)&Wr[ga];
        *(float4*)&si[row * PWS + c4 * 4] = *(const float4*)&Wi[ga];
    }
    __syncthreads();

    uint4* O = mat ? g_WR : g_WK;
    const size_t obase = ((size_t)(panel * 3) * 64 + kb) * TU4;

#pragma unroll
    for (int t = 0; t < 2; t++) {
        const int x = tid + t * 256;
        const int n16 = x >> 6, k16 = (x >> 5) & 1, lane = x & 31;
        const int grp = lane >> 2, tig = lane & 3;
        const int c = n16 * 16 + grp;
        const int k0 = k16 * 16 + tig * 2;

        float wr[8], wi[8];
#pragma unroll
        for (int hc = 0; hc < 2; hc++) {      // col c, c+8
            const int cc = c + hc * 8;
            wr[hc*4+0] = sr[k0 * PWS + cc];       wi[hc*4+0] = si[k0 * PWS + cc];
            wr[hc*4+1] = sr[(k0+1) * PWS + cc];   wi[hc*4+1] = si[(k0+1) * PWS + cc];
            wr[hc*4+2] = sr[(k0+8) * PWS + cc];   wi[hc*4+2] = si[(k0+8) * PWS + cc];
            wr[hc*4+3] = sr[(k0+9) * PWS + cc];   wi[hc*4+3] = si[(k0+9) * PWS + cc];
        }
        uint4 v0, v1, v2;
        v0.x = packh2(wr[0], wr[1]); v0.y = packh2(wr[2], wr[3]);
        v0.z = packh2(wr[4], wr[5]); v0.w = packh2(wr[6], wr[7]);
        v1.x = packh2(wi[0], wi[1]); v1.y = packh2(wi[2], wi[3]);
        v1.z = packh2(wi[4], wi[5]); v1.w = packh2(wi[6], wi[7]);
        v2.x = packh2(wr[0]+wi[0], wr[1]+wi[1]); v2.y = packh2(wr[2]+wi[2], wr[3]+wi[3]);
        v2.z = packh2(wr[4]+wi[4], wr[5]+wi[5]); v2.w = packh2(wr[6]+wi[6], wr[7]+wi[7]);

        O[obase + x]             = v0;
        O[obase + BSTR + x]      = v1;
        O[obase + 2 * BSTR + x]  = v2;
    }
}

// ============================================================================
// prep_a: fp16 A-fragment panels for inputs and h.
// A-fragment uint4 (m16n8k16, row-major A), index x in [0,512):
//   m16 = x>>6, k16 = (x>>5)&1, lane = x&31, grp = lane>>2, tig = lane&3
//   r = m16*16+grp, k0 = k16*16+tig*2
//   halves = {A[r,k0],A[r,k0+1], A[r+8,k0],A[r+8,k0+1],
//             A[r,k0+8],A[r,k0+9], A[r+8,k0+8],A[r+8,k0+9]}
// Layout: [mp(8)][batch(3)][kb(64)][512 u4]; batch 0=re, 1=im, 2=im-re.
// ============================================================================
#define PAS 36

__global__ __launch_bounds__(256) void prep_a(
    const float* __restrict__ in0, const float* __restrict__ in1)
{
    __shared__ float s0[128 * PAS], s1[128 * PAS];
    const int tid = threadIdx.x;
    const int b = blockIdx.x;                 // 0..1023
    const int src = b >> 9;
    const int rem = b & 511;
    const int mp = rem >> 6;
    const int kb = rem & 63;

    const float* A = src ? in1 : in0;

#pragma unroll
    for (int t = 0; t < 8; t++) {
        const int idx = tid + t * 256;        // 2048 f4: half(2) x row(128) x c4(8)
        const int half_ = idx >> 10;
        const int i2 = idx & 1023;
        const int row = i2 >> 3, c4 = i2 & 7;
        const float4 v = *(const float4*)&A[(size_t)(mp * 128 + row) * 4096
                                            + half_ * 2048 + kb * 32 + c4 * 4];
        float* s = half_ ? s1 : s0;
        *(float4*)&s[row * PAS + c4 * 4] = v;
    }
    __syncthreads();

    uint4* O = src ? g_HF : g_AF;
    const size_t obase = ((size_t)(mp * 3) * 64 + kb) * TU4;

#pragma unroll
    for (int t = 0; t < 2; t++) {
        const int x = tid + t * 256;
        const int m16 = x >> 6, k16 = (x >> 5) & 1, lane = x & 31;
        const int grp = lane >> 2, tig = lane & 3;
        const int r = m16 * 16 + grp;
        const int k0 = k16 * 16 + tig * 2;

        float re[8], im[8];
#pragma unroll
        for (int hk = 0; hk < 2; hk++) {      // k0, k0+8
            const int kk = k0 + hk * 8;
            re[hk*4+0] = s0[r * PAS + kk];         im[hk*4+0] = s1[r * PAS + kk];
            re[hk*4+1] = s0[r * PAS + kk + 1];     im[hk*4+1] = s1[r * PAS + kk + 1];
            re[hk*4+2] = s0[(r+8) * PAS + kk];     im[hk*4+2] = s1[(r+8) * PAS + kk];
            re[hk*4+3] = s0[(r+8) * PAS + kk + 1]; im[hk*4+3] = s1[(r+8) * PAS + kk + 1];
        }
        uint4 v0, v1, v2;
        v0.x = packh2(re[0], re[1]); v0.y = packh2(re[2], re[3]);
        v0.z = packh2(re[4], re[5]); v0.w = packh2(re[6], re[7]);
        v1.x = packh2(im[0], im[1]); v1.y = packh2(im[2], im[3]);
        v1.z = packh2(im[4], im[5]); v1.w = packh2(im[6], im[7]);
        v2.x = packh2(im[0]-re[0], im[1]-re[1]); v2.y = packh2(im[2]-re[2], im[3]-re[3]);
        v2.z = packh2(im[4]-re[4], im[5]-re[5]); v2.w = packh2(im[6]-re[6], im[7]-re[7]);

        O[obase + x]             = v0;
        O[obase + BSTR + x]      = v1;
        O[obase + 2 * BSTR + x]  = v2;
    }
}

// ============================================================================
// gemm_frag (fp16): 128x128 CTA tile, 4 warps of 64x64, BK=32 (2 k16 steps),
// 4-stage cp.async, batch/split-K via blockIdx.z.
// ============================================================================
#define STAGES 4
#define STG_BYTES 16384                // A 8KB + B 8KB
#define GSMEM (STAGES * STG_BYTES)     // 64KB

__global__ __launch_bounds__(128, 2) void gemm_frag(
    const uint4* __restrict__ Ap, const uint4* __restrict__ Bp,
    float* __restrict__ C, int Nld, int pOff, int kIters)
{
    extern __shared__ uint4 smu[];
    const uint32_t sbase = smem_u32(smu);
    const int tid = threadIdx.x, wid = tid >> 5, lane = tid & 31;
    const int grp = lane >> 2, tig = lane & 3;
    const int mp = blockIdx.y;
    const int z = blockIdx.z;
    const int batch = z % 3, half_ = z / 3;
    const int panel = blockIdx.x + pOff;
    const int kO = half_ * kIters;

    const uint4* At = Ap + (size_t)(mp * 3 + batch) * BSTR + (size_t)kO * TU4;
    const uint4* Bt = Bp + (size_t)(panel * 3 + batch) * BSTR + (size_t)kO * TU4;
    float* Cb = C + (size_t)z * 1024 * Nld;

    const int wm4 = (wid & 1) * 4;     // A m16-block base
    const int wn4 = (wid >> 1) * 4;    // B n16-block base

    float acc[4][8][4];
#pragma unroll
    for (int a = 0; a < 4; a++)
#pragma unroll
        for (int b = 0; b < 8; b++)
#pragma unroll
            for (int c = 0; c < 4; c++) acc[a][b][c] = 0.0f;

    #define ISSUE(kb) do {                                                     \
        const uint32_t _st = sbase + ((kb) % STAGES) * STG_BYTES;              \
        const uint4* _sa = At + (size_t)(kb) * TU4;                            \
        const uint4* _sb = Bt + (size_t)(kb) * TU4;                            \
        _Pragma("unroll")                                                      \
        for (int _i = 0; _i < 4; _i++) {                                       \
            const int _o = tid + _i * 128;                                     \
            cp16s(_st + _o * 16, _sa + _o);                                    \
            cp16s(_st + 8192 + _o * 16, _sb + _o);                             \
        }                                                                      \
    } while (0)

    ISSUE(0);
    asm volatile("cp.async.commit_group;" ::: "memory");
    ISSUE(1);
    asm volatile("cp.async.commit_group;" ::: "memory");
    ISSUE(2);
    asm volatile("cp.async.commit_group;" ::: "memory");

    uint4 af[2][4], bf[2][4];

    for (int kb = 0; kb < kIters; ++kb) {
        asm volatile("cp.async.wait_group 2;" ::: "memory");
        __syncthreads();

        const uint4* As = smu + (kb % STAGES) * 1024;
        const uint4* Bs = As + 512;

#pragma unroll
        for (int t = 0; t < 4; ++t) {
            af[0][t] = As[((wm4 + t) * 2) * 32 + lane];
            bf[0][t] = Bs[((wn4 + t) * 2) * 32 + lane];
        }

#pragma unroll
        for (int ks = 0; ks < 2; ++ks) {
            const int cur = ks;
            if (ks == 0) {
#pragma unroll
                for (int t = 0; t < 4; ++t) {
                    af[1][t] = As[((wm4 + t) * 2 + 1) * 32 + lane];
                    bf[1][t] = Bs[((wn4 + t) * 2 + 1) * 32 + lane];
                }
            }
#pragma unroll
            for (int tm = 0; tm < 4; ++tm) {
                const uint32_t* a = (const uint32_t*)&af[cur][tm];
#pragma unroll
                for (int p = 0; p < 4; ++p) {
                    const uint32_t* bu = (const uint32_t*)&bf[cur][p];
                    mma_f16(acc[tm][p * 2],     a, bu[0], bu[1]);
                    mma_f16(acc[tm][p * 2 + 1], a, bu[2], bu[3]);
                }
            }
        }

        if (kb + 3 < kIters) ISSUE(kb + 3);
        asm volatile("cp.async.commit_group;" ::: "memory");
    }

#pragma unroll
    for (int tm = 0; tm < 4; ++tm) {
#pragma unroll
        for (int tn = 0; tn < 8; ++tn) {
            const int m0 = mp * 128 + (wid & 1) * 64 + tm * 16 + grp;
            const int n0 = blockIdx.x * 128 + (wid >> 1) * 64 + tn * 8 + tig * 2;
            *(float2*)&Cb[(size_t)m0 * Nld + n0]       = make_float2(acc[tm][tn][0], acc[tm][tn][1]);
            *(float2*)&Cb[(size_t)(m0 + 8) * Nld + n0] = make_float2(acc[tm][tn][2], acc[tm][tn][3]);
        }
    }
}

// ---------------------------------------------------------------- elementwise
__device__ __forceinline__ float hsig(float x) {
    return fminf(fmaxf(0.2f * x + 0.5f, 0.0f), 1.0f);
}

// z,r gates (Gauss combine) + RH fragments (fp16, 3 batches).
__global__ void ew_zr(const float* __restrict__ P, const float* __restrict__ Q,
                      const float* __restrict__ h, const float* __restrict__ rb,
                      const float* __restrict__ ib, float* __restrict__ Z,
                      __half* __restrict__ RHp)
{
    const int i = blockIdx.x * blockDim.x + threadIdx.x;  // 1024 x 512 f4
    const int m = i >> 9;
    const int jj = (i & 511) << 2;                        // j in [0,2048)

    const size_t PX = (size_t)1024 * 6144, QX = (size_t)1024 * 4096;
    const float* P1 = P + (size_t)m * 6144;
    const float* Q1 = Q + (size_t)m * 4096;

    float4 p1z = *(const float4*)&P1[jj],        p2z = *(const float4*)&P1[PX + jj],
           p3z = *(const float4*)&P1[2*PX + jj];
    float4 p1r = *(const float4*)&P1[2048 + jj], p2r = *(const float4*)&P1[PX + 2048 + jj],
           p3r = *(const float4*)&P1[2*PX + 2048 + jj];
    float4 q1z = *(const float4*)&Q1[jj],        q2z = *(const float4*)&Q1[QX + jj],
           q3z = *(const float4*)&Q1[2*QX + jj];
    float4 q1r = *(const float4*)&Q1[2048 + jj], q2r = *(const float4*)&Q1[QX + 2048 + jj],
           q3r = *(const float4*)&Q1[2*QX + 2048 + jj];

    float4 hre = *(const float4*)&h[(size_t)m * 4096 + jj];
    float4 him = *(const float4*)&h[(size_t)m * 4096 + 2048 + jj];
    float4 bzr = *(const float4*)&rb[jj],        bzi = *(const float4*)&ib[jj];
    float4 brr = *(const float4*)&rb[2048 + jj], bri = *(const float4*)&ib[2048 + jj];

    float zre[4], zim[4], vre[4], vim[4];
#pragma unroll
    for (int c = 0; c < 4; c++) {
        float P1z = (&p1z.x)[c], P2z = (&p2z.x)[c], P3z = (&p3z.x)[c];
        float P1r = (&p1r.x)[c], P2r = (&p2r.x)[c], P3r = (&p3r.x)[c];
        float Q1z = (&q1z.x)[c], Q2z = (&q2z.x)[c], Q3z = (&q3z.x)[c];
        float Q1r = (&q1r.x)[c], Q2r = (&q2r.x)[c], Q3r = (&q3r.x)[c];
        zre[c] = hsig(P1z + P2z + (&bzr.x)[c] + Q1z + Q2z);
        zim[c] = hsig(P3z + P1z - P2z + (&bzi.x)[c] + Q3z + Q1z - Q2z);
        float rre = hsig(P1r + P2r + (&brr.x)[c] + Q1r + Q2r);
        float rim = hsig(P3r + P1r - P2r + (&bri.x)[c] + Q3r + Q1r - Q2r);
        vre[c] = rre * (&hre.x)[c];
        vim[c] = rim * (&him.x)[c];
    }

    *(float4*)&Z[(size_t)m * 4096 + jj]        = make_float4(zre[0], zre[1], zre[2], zre[3]);
    *(float4*)&Z[(size_t)m * 4096 + 2048 + jj] = make_float4(zim[0], zim[1], zim[2], zim[3]);

    // fp16 A-fragment scatter: batches 0(re),1(im),2(im-re)
    const int mp = m >> 7, m16 = (m >> 4) & 7;
    const int rr = m & 15, grpm = rr & 7, hi = rr >> 3;
    const int kb = jj >> 5, k16 = (jj >> 4) & 1;
    const int jmk = jj & 15, tig0 = (jmk & 7) >> 1, hiK = jmk >> 3;
    const int pos = hiK * 4 + hi * 2;
    const size_t HBSTR = (size_t)64 * 4096;              // halves per batch panel
    size_t base = ((size_t)(mp * 3) * 64 + kb) * 4096
                + ((size_t)((m16 * 2 + k16) * 32 + grpm * 4) * 8) + pos;

    __half2 a0 = __floats2half2_rn(vre[0], vre[1]);
    __half2 a1 = __floats2half2_rn(vre[2], vre[3]);
    __half2 b0 = __floats2half2_rn(vim[0], vim[1]);
    __half2 b1 = __floats2half2_rn(vim[2], vim[3]);
    __half2 c0 = __floats2half2_rn(vim[0]-vre[0], vim[1]-vre[1]);
    __half2 c1 = __floats2half2_rn(vim[2]-vre[2], vim[3]-vre[3]);

    *(__half2*)&RHp[base + (size_t)tig0 * 8]                       = a0;
    *(__half2*)&RHp[base + (size_t)(tig0 + 1) * 8]                 = a1;
    *(__half2*)&RHp[base + HBSTR + (size_t)tig0 * 8]               = b0;
    *(__half2*)&RHp[base + HBSTR + (size_t)(tig0 + 1) * 8]         = b1;
    *(__half2*)&RHp[base + 2 * HBSTR + (size_t)tig0 * 8]           = c0;
    *(__half2*)&RHp[base + 2 * HBSTR + (size_t)(tig0 + 1) * 8]     = c1;
}

// final blend (Gauss combine, split-K halves summed here)
__global__ void ew_out(const float* __restrict__ P, const float* __restrict__ R,
                       const float* __restrict__ h, const float* __restrict__ rb,
                       const float* __restrict__ ib, const float* __restrict__ Z,
                       float* __restrict__ out)
{
    const int i = blockIdx.x * blockDim.x + threadIdx.x;
    const int m = i >> 9;
    const int jj = (i & 511) << 2;

    const size_t PX = (size_t)1024 * 6144, RX = (size_t)1024 * 2048;
    const float* P1 = P + (size_t)m * 6144;
    const float* R1 = R + (size_t)m * 2048;

    float4 p1 = *(const float4*)&P1[4096 + jj],      p2 = *(const float4*)&P1[PX + 4096 + jj],
           p3 = *(const float4*)&P1[2*PX + 4096 + jj];
    float4 r1a = *(const float4*)&R1[jj],        r1b = *(const float4*)&R1[3*RX + jj];
    float4 r2a = *(const float4*)&R1[RX + jj],   r2b = *(const float4*)&R1[4*RX + jj];
    float4 r3a = *(const float4*)&R1[2*RX + jj], r3b = *(const float4*)&R1[5*RX + jj];

    float4 hre = *(const float4*)&h[(size_t)m * 4096 + jj];
    float4 him = *(const float4*)&h[(size_t)m * 4096 + 2048 + jj];
    float4 zre = *(const float4*)&Z[(size_t)m * 4096 + jj];
    float4 zim = *(const float4*)&Z[(size_t)m * 4096 + 2048 + jj];
    float4 bhr = *(const float4*)&rb[4096 + jj], bhi = *(const float4*)&ib[4096 + jj];

    float ore[4], oim[4];
#pragma unroll
    for (int c = 0; c < 4; c++) {
        float A1 = (&p1.x)[c], A2 = (&p2.x)[c], A3 = (&p3.x)[c];
        float B1 = (&r1a.x)[c] + (&r1b.x)[c];
        float B2 = (&r2a.x)[c] + (&r2b.x)[c];
        float B3 = (&r3a.x)[c] + (&r3b.x)[c];
        float xre = A1 + A2 + (&bhr.x)[c] + B1 + B2;
        float xim = A3 + A1 - A2 + (&bhi.x)[c] + B3 + B1 - B2;
        float tre = tanhf(xre), tim = tanhf(xim);
        float Zr = (&zre.x)[c], Zi = (&zim.x)[c];
        ore[c] = Zr * (&hre.x)[c] + (1.0f - Zr) * tre;
        oim[c] = Zi * (&him.x)[c] + (1.0f - Zi) * tim;
    }
    *(float4*)&out[(size_t)m * 4096 + jj]        = make_float4(ore[0], ore[1], ore[2], ore[3]);
    *(float4*)&out[(size_t)m * 4096 + 2048 + jj] = make_float4(oim[0], oim[1], oim[2], oim[3]);
}

// --------------------------------------------------------------------- launch
extern "C" void kernel_launch(void* const* d_in, const int* in_sizes, int n_in,
                              void* d_out, int out_size)
{
    const float* inputs = (const float*)d_in[0];
    const float* h_tm1  = (const float*)d_in[1];
    const float* rk     = (const float*)d_in[2];
    const float* ik     = (const float*)d_in[3];
    const float* rrk    = (const float*)d_in[4];
    const float* irk    = (const float*)d_in[5];
    const float* rb     = (const float*)d_in[6];
    const float* ib     = (const float*)d_in[7];
    float* out = (float*)d_out;

    uint4 *pWK, *pWR, *pAF, *pHF, *pRHF;
    float *pP, *pQ, *pR, *pZ;
    cudaGetSymbolAddress((void**)&pWK,  g_WK);
    cudaGetSymbolAddress((void**)&pWR,  g_WR);
    cudaGetSymbolAddress((void**)&pAF,  g_AF);
    cudaGetSymbolAddress((void**)&pHF,  g_HF);
    cudaGetSymbolAddress((void**)&pRHF, g_RHF);
    cudaGetSymbolAddress((void**)&pP,   g_P);
    cudaGetSymbolAddress((void**)&pQ,   g_Q);
    cudaGetSymbolAddress((void**)&pR,   g_R);
    cudaGetSymbolAddress((void**)&pZ,   g_Z);

    cudaFuncSetAttribute(gemm_frag, cudaFuncAttributeMaxDynamicSharedMemorySize, GSMEM);

    // materialize fp16 fragment operands (coalesced, smem-staged)
    prep_w<<<6144, 256>>>(rk, ik, rrk, irk);
    prep_a<<<1024, 256>>>(inputs, h_tm1);

    // P = {Ar,Ai,Ai-Ar} @ {Kr,Ki,Kr+Ki}   (N = 6144, 3 batches, K = 2048)
    gemm_frag<<<dim3(48, 8, 3), 128, GSMEM>>>(pAF, pWK, pP, 6144, 0, KITERS);
    // Q = h-batches @ R-batches, gates z,r (N = 4096, K = 2048)
    gemm_frag<<<dim3(32, 8, 3), 128, GSMEM>>>(pHF, pWR, pQ, 4096, 0, KITERS);
    // gates + RH fragments
    ew_zr<<<2048, 256>>>(pP, pQ, h_tm1, rb, ib, pZ, (__half*)pRHF);
    // R = RH-batches @ R-batches, gate h (N = 2048, panels 32..47, split-K x2)
    gemm_frag<<<dim3(16, 8, 6), 128, GSMEM>>>(pRHF, pWR, pR, 2048, 32, 32);
    // out
    ew_out<<<2048, 256>>>(pP, pR, h_tm1, rb, ib, pZ, out);
}

// round 10
// speedup vs baseline: 3.9341x; 1.0280x over previous
#include <cuda_runtime.h>
#include <cuda_fp16.h>
#include <cstdint>
#include <cmath>

// ============================================================================
// CGRU cell, B=1024, UNITS=2048 — Gauss 3-mult complex GEMM, FP16 mma.sync.
//   Re(A@conj(W)) = P1 + P2,  Im = P3 + P1 - P2
//   P1 = Ar@Wr, P2 = Ai@Wi, P3 = (Ai-Ar)@(Wr+Wi)   (each K=2048)
// v5: two-stream fork/join capture — recurrent-weight prep + Q GEMM on a side
// stream, overlapping the P GEMM. Kernels identical to round 9 otherwise.
// ============================================================================

#define KITERS 64                       // 2048 / 32
#define TU4 512                         // uint4 per 128x32 fp16 tile
#define BSTR ((size_t)KITERS * TU4)     // uint4 per (unit,batch) fragment panel

// ------------------------------ scratch (device globals, allocation-free) --
__device__ uint4 g_WK [(size_t)48 * 3 * BSTR];
__device__ uint4 g_WR [(size_t)48 * 3 * BSTR];
__device__ uint4 g_AF [(size_t)8  * 3 * BSTR];
__device__ uint4 g_HF [(size_t)8  * 3 * BSTR];
__device__ uint4 g_RHF[(size_t)8  * 3 * BSTR];
__device__ float g_P  [(size_t)3 * 1024 * 6144];
__device__ float g_Q  [(size_t)3 * 1024 * 4096];
__device__ float g_R  [(size_t)6 * 1024 * 2048];
__device__ float g_Z  [(size_t)1024 * 4096];

// ----------------------------------------------------------------- helpers --
__device__ __forceinline__ void cp16s(uint32_t d, const void* s) {
    asm volatile("cp.async.cg.shared.global [%0], [%1], 16;" :: "r"(d), "l"(s));
}
__device__ __forceinline__ uint32_t smem_u32(const void* p) {
    uint32_t a;
    asm("{ .reg .u64 t; cvta.to.shared.u64 t, %1; cvt.u32.u64 %0, t; }" : "=r"(a) : "l"(p));
    return a;
}
__device__ __forceinline__ void mma_f16(float* c, const uint32_t* a, uint32_t b0, uint32_t b1) {
    asm volatile(
        "mma.sync.aligned.m16n8k16.row.col.f32.f16.f16.f32 "
        "{%0,%1,%2,%3},{%4,%5,%6,%7},{%8,%9},{%0,%1,%2,%3};"
        : "+f"(c[0]), "+f"(c[1]), "+f"(c[2]), "+f"(c[3])
        : "r"(a[0]), "r"(a[1]), "r"(a[2]), "r"(a[3]), "r"(b0), "r"(b1));
}
__device__ __forceinline__ uint32_t packh2(float a, float b) {
    __half2 h = __floats2half2_rn(a, b);
    return *(uint32_t*)&h;
}

// ============================================================================
// prep_w: fp16 B-fragment panels for ONE matrix (Wr, Wi given), 3 Gauss
// batches. Layout: [panel(48)][batch(3)][kb(64)][512 u4].
// ============================================================================
#define PWS 136

__global__ __launch_bounds__(256) void prep_w(
    const float* __restrict__ Wr, const float* __restrict__ Wi,
    uint4* __restrict__ O)
{
    __shared__ float sr[32 * PWS], si[32 * PWS];
    const int tid = threadIdx.x;
    const int b = blockIdx.x;                 // 0..3071
    const int panel = b >> 6;
    const int kb = b & 63;

    const size_t gbase = (size_t)(kb * 32) * 6144 + panel * 128;

#pragma unroll
    for (int t = 0; t < 4; t++) {
        const int idx = tid + t * 256;
        const int row = idx >> 5, c4 = idx & 31;
        const size_t ga = gbase + (size_t)row * 6144 + c4 * 4;
        *(float4*)&sr[row * PWS + c4 * 4] = *(const float4*)&Wr[ga];
        *(float4*)&si[row * PWS + c4 * 4] = *(const float4*)&Wi[ga];
    }
    __syncthreads();

    const size_t obase = ((size_t)(panel * 3) * 64 + kb) * TU4;

#pragma unroll
    for (int t = 0; t < 2; t++) {
        const int x = tid + t * 256;
        const int n16 = x >> 6, k16 = (x >> 5) & 1, lane = x & 31;
        const int grp = lane >> 2, tig = lane & 3;
        const int c = n16 * 16 + grp;
        const int k0 = k16 * 16 + tig * 2;

        float wr[8], wi[8];
#pragma unroll
        for (int hc = 0; hc < 2; hc++) {
            const int cc = c + hc * 8;
            wr[hc*4+0] = sr[k0 * PWS + cc];       wi[hc*4+0] = si[k0 * PWS + cc];
            wr[hc*4+1] = sr[(k0+1) * PWS + cc];   wi[hc*4+1] = si[(k0+1) * PWS + cc];
            wr[hc*4+2] = sr[(k0+8) * PWS + cc];   wi[hc*4+2] = si[(k0+8) * PWS + cc];
            wr[hc*4+3] = sr[(k0+9) * PWS + cc];   wi[hc*4+3] = si[(k0+9) * PWS + cc];
        }
        uint4 v0, v1, v2;
        v0.x = packh2(wr[0], wr[1]); v0.y = packh2(wr[2], wr[3]);
        v0.z = packh2(wr[4], wr[5]); v0.w = packh2(wr[6], wr[7]);
        v1.x = packh2(wi[0], wi[1]); v1.y = packh2(wi[2], wi[3]);
        v1.z = packh2(wi[4], wi[5]); v1.w = packh2(wi[6], wi[7]);
        v2.x = packh2(wr[0]+wi[0], wr[1]+wi[1]); v2.y = packh2(wr[2]+wi[2], wr[3]+wi[3]);
        v2.z = packh2(wr[4]+wi[4], wr[5]+wi[5]); v2.w = packh2(wr[6]+wi[6], wr[7]+wi[7]);

        O[obase + x]             = v0;
        O[obase + BSTR + x]      = v1;
        O[obase + 2 * BSTR + x]  = v2;
    }
}

// ============================================================================
// prep_a: fp16 A-fragment panels for inputs and h.
// Layout: [mp(8)][batch(3)][kb(64)][512 u4]; batch 0=re, 1=im, 2=im-re.
// ============================================================================
#define PAS 36

__global__ __launch_bounds__(256) void prep_a(
    const float* __restrict__ in0, const float* __restrict__ in1)
{
    __shared__ float s0[128 * PAS], s1[128 * PAS];
    const int tid = threadIdx.x;
    const int b = blockIdx.x;                 // 0..1023
    const int src = b >> 9;
    const int rem = b & 511;
    const int mp = rem >> 6;
    const int kb = rem & 63;

    const float* A = src ? in1 : in0;

#pragma unroll
    for (int t = 0; t < 8; t++) {
        const int idx = tid + t * 256;
        const int half_ = idx >> 10;
        const int i2 = idx & 1023;
        const int row = i2 >> 3, c4 = i2 & 7;
        const float4 v = *(const float4*)&A[(size_t)(mp * 128 + row) * 4096
                                            + half_ * 2048 + kb * 32 + c4 * 4];
        float* s = half_ ? s1 : s0;
        *(float4*)&s[row * PAS + c4 * 4] = v;
    }
    __syncthreads();

    uint4* O = src ? g_HF : g_AF;
    const size_t obase = ((size_t)(mp * 3) * 64 + kb) * TU4;

#pragma unroll
    for (int t = 0; t < 2; t++) {
        const int x = tid + t * 256;
        const int m16 = x >> 6, k16 = (x >> 5) & 1, lane = x & 31;
        const int grp = lane >> 2, tig = lane & 3;
        const int r = m16 * 16 + grp;
        const int k0 = k16 * 16 + tig * 2;

        float re[8], im[8];
#pragma unroll
        for (int hk = 0; hk < 2; hk++) {
            const int kk = k0 + hk * 8;
            re[hk*4+0] = s0[r * PAS + kk];         im[hk*4+0] = s1[r * PAS + kk];
            re[hk*4+1] = s0[r * PAS + kk + 1];     im[hk*4+1] = s1[r * PAS + kk + 1];
            re[hk*4+2] = s0[(r+8) * PAS + kk];     im[hk*4+2] = s1[(r+8) * PAS + kk];
            re[hk*4+3] = s0[(r+8) * PAS + kk + 1]; im[hk*4+3] = s1[(r+8) * PAS + kk + 1];
        }
        uint4 v0, v1, v2;
        v0.x = packh2(re[0], re[1]); v0.y = packh2(re[2], re[3]);
        v0.z = packh2(re[4], re[5]); v0.w = packh2(re[6], re[7]);
        v1.x = packh2(im[0], im[1]); v1.y = packh2(im[2], im[3]);
        v1.z = packh2(im[4], im[5]); v1.w = packh2(im[6], im[7]);
        v2.x = packh2(im[0]-re[0], im[1]-re[1]); v2.y = packh2(im[2]-re[2], im[3]-re[3]);
        v2.z = packh2(im[4]-re[4], im[5]-re[5]); v2.w = packh2(im[6]-re[6], im[7]-re[7]);

        O[obase + x]             = v0;
        O[obase + BSTR + x]      = v1;
        O[obase + 2 * BSTR + x]  = v2;
    }
}

// ============================================================================
// gemm_frag (fp16): 128x128 CTA tile, 4 warps of 64x64, BK=32 (2 k16 steps),
// 4-stage cp.async, batch/split-K via blockIdx.z.
// ============================================================================
#define STAGES 4
#define STG_BYTES 16384
#define GSMEM (STAGES * STG_BYTES)

__global__ __launch_bounds__(128, 2) void gemm_frag(
    const uint4* __restrict__ Ap, const uint4* __restrict__ Bp,
    float* __restrict__ C, int Nld, int pOff, int kIters)
{
    extern __shared__ uint4 smu[];
    const uint32_t sbase = smem_u32(smu);
    const int tid = threadIdx.x, wid = tid >> 5, lane = tid & 31;
    const int grp = lane >> 2, tig = lane & 3;
    const int mp = blockIdx.y;
    const int z = blockIdx.z;
    const int batch = z % 3, half_ = z / 3;
    const int panel = blockIdx.x + pOff;
    const int kO = half_ * kIters;

    const uint4* At = Ap + (size_t)(mp * 3 + batch) * BSTR + (size_t)kO * TU4;
    const uint4* Bt = Bp + (size_t)(panel * 3 + batch) * BSTR + (size_t)kO * TU4;
    float* Cb = C + (size_t)z * 1024 * Nld;

    const int wm4 = (wid & 1) * 4;
    const int wn4 = (wid >> 1) * 4;

    float acc[4][8][4];
#pragma unroll
    for (int a = 0; a < 4; a++)
#pragma unroll
        for (int b = 0; b < 8; b++)
#pragma unroll
            for (int c = 0; c < 4; c++) acc[a][b][c] = 0.0f;

    #define ISSUE(kb) do {                                                     \
        const uint32_t _st = sbase + ((kb) % STAGES) * STG_BYTES;              \
        const uint4* _sa = At + (size_t)(kb) * TU4;                            \
        const uint4* _sb = Bt + (size_t)(kb) * TU4;                            \
        _Pragma("unroll")                                                      \
        for (int _i = 0; _i < 4; _i++) {                                       \
            const int _o = tid + _i * 128;                                     \
            cp16s(_st + _o * 16, _sa + _o);                                    \
            cp16s(_st + 8192 + _o * 16, _sb + _o);                             \
        }                                                                      \
    } while (0)

    ISSUE(0);
    asm volatile("cp.async.commit_group;" ::: "memory");
    ISSUE(1);
    asm volatile("cp.async.commit_group;" ::: "memory");
    ISSUE(2);
    asm volatile("cp.async.commit_group;" ::: "memory");

    uint4 af[2][4], bf[2][4];

    for (int kb = 0; kb < kIters; ++kb) {
        asm volatile("cp.async.wait_group 2;" ::: "memory");
        __syncthreads();

        const uint4* As = smu + (kb % STAGES) * 1024;
        const uint4* Bs = As + 512;

#pragma unroll
        for (int t = 0; t < 4; ++t) {
            af[0][t] = As[((wm4 + t) * 2) * 32 + lane];
            bf[0][t] = Bs[((wn4 + t) * 2) * 32 + lane];
        }

#pragma unroll
        for (int ks = 0; ks < 2; ++ks) {
            const int cur = ks;
            if (ks == 0) {
#pragma unroll
                for (int t = 0; t < 4; ++t) {
                    af[1][t] = As[((wm4 + t) * 2 + 1) * 32 + lane];
                    bf[1][t] = Bs[((wn4 + t) * 2 + 1) * 32 + lane];
                }
            }
#pragma unroll
            for (int tm = 0; tm < 4; ++tm) {
                const uint32_t* a = (const uint32_t*)&af[cur][tm];
#pragma unroll
                for (int p = 0; p < 4; ++p) {
                    const uint32_t* bu = (const uint32_t*)&bf[cur][p];
                    mma_f16(acc[tm][p * 2],     a, bu[0], bu[1]);
                    mma_f16(acc[tm][p * 2 + 1], a, bu[2], bu[3]);
                }
            }
        }

        if (kb + 3 < kIters) ISSUE(kb + 3);
        asm volatile("cp.async.commit_group;" ::: "memory");
    }

#pragma unroll
    for (int tm = 0; tm < 4; ++tm) {
#pragma unroll
        for (int tn = 0; tn < 8; ++tn) {
            const int m0 = mp * 128 + (wid & 1) * 64 + tm * 16 + grp;
            const int n0 = blockIdx.x * 128 + (wid >> 1) * 64 + tn * 8 + tig * 2;
            *(float2*)&Cb[(size_t)m0 * Nld + n0]       = make_float2(acc[tm][tn][0], acc[tm][tn][1]);
            *(float2*)&Cb[(size_t)(m0 + 8) * Nld + n0] = make_float2(acc[tm][tn][2], acc[tm][tn][3]);
        }
    }
}

// ---------------------------------------------------------------- elementwise
__device__ __forceinline__ float hsig(float x) {
    return fminf(fmaxf(0.2f * x + 0.5f, 0.0f), 1.0f);
}

__global__ void ew_zr(const float* __restrict__ P, const float* __restrict__ Q,
                      const float* __restrict__ h, const float* __restrict__ rb,
                      const float* __restrict__ ib, float* __restrict__ Z,
                      __half* __restrict__ RHp)
{
    const int i = blockIdx.x * blockDim.x + threadIdx.x;
    const int m = i >> 9;
    const int jj = (i & 511) << 2;

    const size_t PX = (size_t)1024 * 6144, QX = (size_t)1024 * 4096;
    const float* P1 = P + (size_t)m * 6144;
    const float* Q1 = Q + (size_t)m * 4096;

    float4 p1z = *(const float4*)&P1[jj],        p2z = *(const float4*)&P1[PX + jj],
           p3z = *(const float4*)&P1[2*PX + jj];
    float4 p1r = *(const float4*)&P1[2048 + jj], p2r = *(const float4*)&P1[PX + 2048 + jj],
           p3r = *(const float4*)&P1[2*PX + 2048 + jj];
    float4 q1z = *(const float4*)&Q1[jj],        q2z = *(const float4*)&Q1[QX + jj],
           q3z = *(const float4*)&Q1[2*QX + jj];
    float4 q1r = *(const float4*)&Q1[2048 + jj], q2r = *(const float4*)&Q1[QX + 2048 + jj],
           q3r = *(const float4*)&Q1[2*QX + 2048 + jj];

    float4 hre = *(const float4*)&h[(size_t)m * 4096 + jj];
    float4 him = *(const float4*)&h[(size_t)m * 4096 + 2048 + jj];
    float4 bzr = *(const float4*)&rb[jj],        bzi = *(const float4*)&ib[jj];
    float4 brr = *(const float4*)&rb[2048 + jj], bri = *(const float4*)&ib[2048 + jj];

    float zre[4], zim[4], vre[4], vim[4];
#pragma unroll
    for (int c = 0; c < 4; c++) {
        float P1z = (&p1z.x)[c], P2z = (&p2z.x)[c], P3z = (&p3z.x)[c];
        float P1r = (&p1r.x)[c], P2r = (&p2r.x)[c], P3r = (&p3r.x)[c];
        float Q1z = (&q1z.x)[c], Q2z = (&q2z.x)[c], Q3z = (&q3z.x)[c];
        float Q1r = (&q1r.x)[c], Q2r = (&q2r.x)[c], Q3r = (&q3r.x)[c];
        zre[c] = hsig(P1z + P2z + (&bzr.x)[c] + Q1z + Q2z);
        zim[c] = hsig(P3z + P1z - P2z + (&bzi.x)[c] + Q3z + Q1z - Q2z);
        float rre = hsig(P1r + P2r + (&brr.x)[c] + Q1r + Q2r);
        float rim = hsig(P3r + P1r - P2r + (&bri.x)[c] + Q3r + Q1r - Q2r);
        vre[c] = rre * (&hre.x)[c];
        vim[c] = rim * (&him.x)[c];
    }

    *(float4*)&Z[(size_t)m * 4096 + jj]        = make_float4(zre[0], zre[1], zre[2], zre[3]);
    *(float4*)&Z[(size_t)m * 4096 + 2048 + jj] = make_float4(zim[0], zim[1], zim[2], zim[3]);

    const int mp = m >> 7, m16 = (m >> 4) & 7;
    const int rr = m & 15, grpm = rr & 7, hi = rr >> 3;
    const int kb = jj >> 5, k16 = (jj >> 4) & 1;
    const int jmk = jj & 15, tig0 = (jmk & 7) >> 1, hiK = jmk >> 3;
    const int pos = hiK * 4 + hi * 2;
    const size_t HBSTR = (size_t)64 * 4096;
    size_t base = ((size_t)(mp * 3) * 64 + kb) * 4096
                + ((size_t)((m16 * 2 + k16) * 32 + grpm * 4) * 8) + pos;

    __half2 a0 = __floats2half2_rn(vre[0], vre[1]);
    __half2 a1 = __floats2half2_rn(vre[2], vre[3]);
    __half2 b0 = __floats2half2_rn(vim[0], vim[1]);
    __half2 b1 = __floats2half2_rn(vim[2], vim[3]);
    __half2 c0 = __floats2half2_rn(vim[0]-vre[0], vim[1]-vre[1]);
    __half2 c1 = __floats2half2_rn(vim[2]-vre[2], vim[3]-vre[3]);

    *(__half2*)&RHp[base + (size_t)tig0 * 8]                   = a0;
    *(__half2*)&RHp[base + (size_t)(tig0 + 1) * 8]             = a1;
    *(__half2*)&RHp[base + HBSTR + (size_t)tig0 * 8]           = b0;
    *(__half2*)&RHp[base + HBSTR + (size_t)(tig0 + 1) * 8]     = b1;
    *(__half2*)&RHp[base + 2 * HBSTR + (size_t)tig0 * 8]       = c0;
    *(__half2*)&RHp[base + 2 * HBSTR + (size_t)(tig0 + 1) * 8] = c1;
}

__global__ void ew_out(const float* __restrict__ P, const float* __restrict__ R,
                       const float* __restrict__ h, const float* __restrict__ rb,
                       const float* __restrict__ ib, const float* __restrict__ Z,
                       float* __restrict__ out)
{
    const int i = blockIdx.x * blockDim.x + threadIdx.x;
    const int m = i >> 9;
    const int jj = (i & 511) << 2;

    const size_t PX = (size_t)1024 * 6144, RX = (size_t)1024 * 2048;
    const float* P1 = P + (size_t)m * 6144;
    const float* R1 = R + (size_t)m * 2048;

    float4 p1 = *(const float4*)&P1[4096 + jj],      p2 = *(const float4*)&P1[PX + 4096 + jj],
           p3 = *(const float4*)&P1[2*PX + 4096 + jj];
    float4 r1a = *(const float4*)&R1[jj],        r1b = *(const float4*)&R1[3*RX + jj];
    float4 r2a = *(const float4*)&R1[RX + jj],   r2b = *(const float4*)&R1[4*RX + jj];
    float4 r3a = *(const float4*)&R1[2*RX + jj], r3b = *(const float4*)&R1[5*RX + jj];

    float4 hre = *(const float4*)&h[(size_t)m * 4096 + jj];
    float4 him = *(const float4*)&h[(size_t)m * 4096 + 2048 + jj];
    float4 zre = *(const float4*)&Z[(size_t)m * 4096 + jj];
    float4 zim = *(const float4*)&Z[(size_t)m * 4096 + 2048 + jj];
    float4 bhr = *(const float4*)&rb[4096 + jj], bhi = *(const float4*)&ib[4096 + jj];

    float ore[4], oim[4];
#pragma unroll
    for (int c = 0; c < 4; c++) {
        float A1 = (&p1.x)[c], A2 = (&p2.x)[c], A3 = (&p3.x)[c];
        float B1 = (&r1a.x)[c] + (&r1b.x)[c];
        float B2 = (&r2a.x)[c] + (&r2b.x)[c];
        float B3 = (&r3a.x)[c] + (&r3b.x)[c];
        float xre = A1 + A2 + (&bhr.x)[c] + B1 + B2;
        float xim = A3 + A1 - A2 + (&bhi.x)[c] + B3 + B1 - B2;
        float tre = tanhf(xre), tim = tanhf(xim);
        float Zr = (&zre.x)[c], Zi = (&zim.x)[c];
        ore[c] = Zr * (&hre.x)[c] + (1.0f - Zr) * tre;
        oim[c] = Zi * (&him.x)[c] + (1.0f - Zi) * tim;
    }
    *(float4*)&out[(size_t)m * 4096 + jj]        = make_float4(ore[0], ore[1], ore[2], ore[3]);
    *(float4*)&out[(size_t)m * 4096 + 2048 + jj] = make_float4(oim[0], oim[1], oim[2], oim[3]);
}

// --------------------------------------------------------------------- launch
extern "C" void kernel_launch(void* const* d_in, const int* in_sizes, int n_in,
                              void* d_out, int out_size)
{
    const float* inputs = (const float*)d_in[0];
    const float* h_tm1  = (const float*)d_in[1];
    const float* rk     = (const float*)d_in[2];
    const float* ik     = (const float*)d_in[3];
    const float* rrk    = (const float*)d_in[4];
    const float* irk    = (const float*)d_in[5];
    const float* rb     = (const float*)d_in[6];
    const float* ib     = (const float*)d_in[7];
    float* out = (float*)d_out;

    uint4 *pWK, *pWR, *pAF, *pHF, *pRHF;
    float *pP, *pQ, *pR, *pZ;
    cudaGetSymbolAddress((void**)&pWK,  g_WK);
    cudaGetSymbolAddress((void**)&pWR,  g_WR);
    cudaGetSymbolAddress((void**)&pAF,  g_AF);
    cudaGetSymbolAddress((void**)&pHF,  g_HF);
    cudaGetSymbolAddress((void**)&pRHF, g_RHF);
    cudaGetSymbolAddress((void**)&pP,   g_P);
    cudaGetSymbolAddress((void**)&pQ,   g_Q);
    cudaGetSymbolAddress((void**)&pR,   g_R);
    cudaGetSymbolAddress((void**)&pZ,   g_Z);

    cudaFuncSetAttribute(gemm_frag, cudaFuncAttributeMaxDynamicSharedMemorySize, GSMEM);

    // side stream + events (host-side objects; created per call, joined before
    // return so the whole DAG hangs off the capture stream)
    cudaStream_t s1;
    cudaStreamCreateWithFlags(&s1, cudaStreamNonBlocking);
    cudaEvent_t eF, eA, eQ;
    cudaEventCreateWithFlags(&eF, cudaEventDisableTiming);
    cudaEventCreateWithFlags(&eA, cudaEventDisableTiming);
    cudaEventCreateWithFlags(&eQ, cudaEventDisableTiming);

    // fork
    cudaEventRecord(eF, 0);
    cudaStreamWaitEvent(s1, eF, 0);

    // s1: recurrent-weight prep (memory-bound) — overlaps s0 prep + P GEMM
    prep_w<<<3072, 256, 0, s1>>>(rrk, irk, pWR);

    // s0: operand prep + input-weight prep + P GEMM
    prep_a<<<1024, 256>>>(inputs, h_tm1);
    cudaEventRecord(eA, 0);
    prep_w<<<3072, 256>>>(rk, ik, pWK);
    gemm_frag<<<dim3(48, 8, 3), 128, GSMEM>>>(pAF, pWK, pP, 6144, 0, KITERS);

    // s1: Q GEMM (needs HF from prep_a, WR from its own stream)
    cudaStreamWaitEvent(s1, eA, 0);
    gemm_frag<<<dim3(32, 8, 3), 128, GSMEM, s1>>>(pHF, pWR, pQ, 4096, 0, KITERS);
    cudaEventRecord(eQ, s1);

    // join: everything below depends on P (s0 order) and Q (event)
    cudaStreamWaitEvent(0, eQ, 0);
    ew_zr<<<2048, 256>>>(pP, pQ, h_tm1, rb, ib, pZ, (__half*)pRHF);
    gemm_frag<<<dim3(16, 8, 6), 128, GSMEM>>>(pRHF, pWR, pR, 2048, 32, 32);
    ew_out<<<2048, 256>>>(pP, pR, h_tm1, rb, ib, pZ, out);
}

// round 11
// speedup vs baseline: 3.9544x; 1.0052x over previous
#include <cuda_runtime.h>
#include <cuda_fp16.h>
#include <cstdint>
#include <cmath>

// ============================================================================
// CGRU cell, B=1024, UNITS=2048 — Gauss 3-mult complex GEMM, FP16 mma.sync.
// v6: concat-K fusion — [A|H] @ [[K],[R]] computes x+recurrent in ONE GEMM
// (K=4096) for gates z,r; gate-h input GEMM (K=2048) fused into the same
// launch as extra panels. 6 launches total, 2 streams.
// ============================================================================

#define TU4 512                          // uint4 per 128x32 fp16 tile
#define ASTRIDE ((size_t)128 * TU4)      // u4 per (unit,batch): 128 kb slots
#define HSTRIDE ((size_t)64 * TU4)       // u4 per (unit,batch): 64 kb slots
#define BSTR HSTRIDE                     // for gemm_frag (HH GEMM)

// ------------------------------ scratch (device globals, allocation-free) --
__device__ uint4 g_AH [(size_t)8  * 3 * ASTRIDE];  // [A|H] fragments  (25MB)
__device__ uint4 g_WZR[(size_t)32 * 3 * ASTRIDE];  // [[Kzr],[Rzr]]    (100MB)
__device__ uint4 g_WH [(size_t)16 * 3 * HSTRIDE];  // Kh               (25MB)
__device__ uint4 g_WRH[(size_t)16 * 3 * HSTRIDE];  // Rh               (25MB)
__device__ uint4 g_RHF[(size_t)8  * 3 * HSTRIDE];  // (r*h) fragments  (12.6MB)
__device__ float g_ZR [(size_t)3 * 1024 * 4096];   // zr GEMM out (50MB)
__device__ float g_XH [(size_t)3 * 1024 * 2048];   // x_h GEMM out (25MB)
__device__ float g_R  [(size_t)6 * 1024 * 2048];   // HH GEMM out (split-K x2)
__device__ float g_Z  [(size_t)1024 * 4096];

// ----------------------------------------------------------------- helpers --
__device__ __forceinline__ void cp16s(uint32_t d, const void* s) {
    asm volatile("cp.async.cg.shared.global [%0], [%1], 16;" :: "r"(d), "l"(s));
}
__device__ __forceinline__ uint32_t smem_u32(const void* p) {
    uint32_t a;
    asm("{ .reg .u64 t; cvta.to.shared.u64 t, %1; cvt.u32.u64 %0, t; }" : "=r"(a) : "l"(p));
    return a;
}
__device__ __forceinline__ void mma_f16(float* c, const uint32_t* a, uint32_t b0, uint32_t b1) {
    asm volatile(
        "mma.sync.aligned.m16n8k16.row.col.f32.f16.f16.f32 "
        "{%0,%1,%2,%3},{%4,%5,%6,%7},{%8,%9},{%0,%1,%2,%3};"
        : "+f"(c[0]), "+f"(c[1]), "+f"(c[2]), "+f"(c[3])
        : "r"(a[0]), "r"(a[1]), "r"(a[2]), "r"(a[3]), "r"(b0), "r"(b1));
}
__device__ __forceinline__ uint32_t packh2(float a, float b) {
    __half2 h = __floats2half2_rn(a, b);
    return *(uint32_t*)&h;
}

// ============================================================================
// prep_w: both weight matrices, fp16 B-fragments into concat layout.
//   mat 0 (rk,ik):  panels 0-31 -> WZR kb 0-63;  panels 32-47 -> WH kb 0-63
//   mat 1 (rrk,irk):panels 0-31 -> WZR kb 64-127; panels 32-47 -> WRH kb 0-63
// ============================================================================
#define PWS 136

__global__ __launch_bounds__(256) void prep_w(
    const float* __restrict__ rk,  const float* __restrict__ ik,
    const float* __restrict__ rrk, const float* __restrict__ irk)
{
    __shared__ float sr[32 * PWS], si[32 * PWS];
    const int tid = threadIdx.x;
    const int b = blockIdx.x;                 // 0..6143
    const int mat = b >= 3072;
    const int rem = b - mat * 3072;
    const int panel = rem >> 6;
    const int kb = rem & 63;

    const float* Wr = mat ? rrk : rk;
    const float* Wi = mat ? irk : ik;
    const size_t gbase = (size_t)(kb * 32) * 6144 + panel * 128;

#pragma unroll
    for (int t = 0; t < 4; t++) {
        const int idx = tid + t * 256;
        const int row = idx >> 5, c4 = idx & 31;
        const size_t ga = gbase + (size_t)row * 6144 + c4 * 4;
        *(float4*)&sr[row * PWS + c4 * 4] = *(const float4*)&Wr[ga];
        *(float4*)&si[row * PWS + c4 * 4] = *(const float4*)&Wi[ga];
    }
    __syncthreads();

    uint4* O;
    size_t obase, bstr;
    if (panel < 32) {
        O = g_WZR;
        obase = ((size_t)(panel * 3) * 128 + mat * 64 + kb) * TU4;
        bstr = ASTRIDE;
    } else {
        O = mat ? g_WRH : g_WH;
        obase = ((size_t)((panel - 32) * 3) * 64 + kb) * TU4;
        bstr = HSTRIDE;
    }

#pragma unroll
    for (int t = 0; t < 2; t++) {
        const int x = tid + t * 256;
        const int n16 = x >> 6, k16 = (x >> 5) & 1, lane = x & 31;
        const int grp = lane >> 2, tig = lane & 3;
        const int c = n16 * 16 + grp;
        const int k0 = k16 * 16 + tig * 2;

        float wr[8], wi[8];
#pragma unroll
        for (int hc = 0; hc < 2; hc++) {
            const int cc = c + hc * 8;
            wr[hc*4+0] = sr[k0 * PWS + cc];       wi[hc*4+0] = si[k0 * PWS + cc];
            wr[hc*4+1] = sr[(k0+1) * PWS + cc];   wi[hc*4+1] = si[(k0+1) * PWS + cc];
            wr[hc*4+2] = sr[(k0+8) * PWS + cc];   wi[hc*4+2] = si[(k0+8) * PWS + cc];
            wr[hc*4+3] = sr[(k0+9) * PWS + cc];   wi[hc*4+3] = si[(k0+9) * PWS + cc];
        }
        uint4 v0, v1, v2;
        v0.x = packh2(wr[0], wr[1]); v0.y = packh2(wr[2], wr[3]);
        v0.z = packh2(wr[4], wr[5]); v0.w = packh2(wr[6], wr[7]);
        v1.x = packh2(wi[0], wi[1]); v1.y = packh2(wi[2], wi[3]);
        v1.z = packh2(wi[4], wi[5]); v1.w = packh2(wi[6], wi[7]);
        v2.x = packh2(wr[0]+wi[0], wr[1]+wi[1]); v2.y = packh2(wr[2]+wi[2], wr[3]+wi[3]);
        v2.z = packh2(wr[4]+wi[4], wr[5]+wi[5]); v2.w = packh2(wr[6]+wi[6], wr[7]+wi[7]);

        O[obase + x]            = v0;
        O[obase + bstr + x]     = v1;
        O[obase + 2 * bstr + x] = v2;
    }
}

// ============================================================================
// prep_a: A-fragments into concat layout [mp(8)][batch(3)][kb(128)][512 u4]:
//   src 0 (inputs) -> kb 0-63, src 1 (h) -> kb 64-127.
// ============================================================================
#define PAS 36

__global__ __launch_bounds__(256) void prep_a(
    const float* __restrict__ in0, const float* __restrict__ in1)
{
    __shared__ float s0[128 * PAS], s1[128 * PAS];
    const int tid = threadIdx.x;
    const int b = blockIdx.x;                 // 0..1023
    const int src = b >> 9;
    const int rem = b & 511;
    const int mp = rem >> 6;
    const int kb = rem & 63;

    const float* A = src ? in1 : in0;

#pragma unroll
    for (int t = 0; t < 8; t++) {
        const int idx = tid + t * 256;
        const int half_ = idx >> 10;
        const int i2 = idx & 1023;
        const int row = i2 >> 3, c4 = i2 & 7;
        const float4 v = *(const float4*)&A[(size_t)(mp * 128 + row) * 4096
                                            + half_ * 2048 + kb * 32 + c4 * 4];
        float* s = half_ ? s1 : s0;
        *(float4*)&s[row * PAS + c4 * 4] = v;
    }
    __syncthreads();

    const size_t obase = ((size_t)(mp * 3) * 128 + src * 64 + kb) * TU4;

#pragma unroll
    for (int t = 0; t < 2; t++) {
        const int x = tid + t * 256;
        const int m16 = x >> 6, k16 = (x >> 5) & 1, lane = x & 31;
        const int grp = lane >> 2, tig = lane & 3;
        const int r = m16 * 16 + grp;
        const int k0 = k16 * 16 + tig * 2;

        float re[8], im[8];
#pragma unroll
        for (int hk = 0; hk < 2; hk++) {
            const int kk = k0 + hk * 8;
            re[hk*4+0] = s0[r * PAS + kk];         im[hk*4+0] = s1[r * PAS + kk];
            re[hk*4+1] = s0[r * PAS + kk + 1];     im[hk*4+1] = s1[r * PAS + kk + 1];
            re[hk*4+2] = s0[(r+8) * PAS + kk];     im[hk*4+2] = s1[(r+8) * PAS + kk];
            re[hk*4+3] = s0[(r+8) * PAS + kk + 1]; im[hk*4+3] = s1[(r+8) * PAS + kk + 1];
        }
        uint4 v0, v1, v2;
        v0.x = packh2(re[0], re[1]); v0.y = packh2(re[2], re[3]);
        v0.z = packh2(re[4], re[5]); v0.w = packh2(re[6], re[7]);
        v1.x = packh2(im[0], im[1]); v1.y = packh2(im[2], im[3]);
        v1.z = packh2(im[4], im[5]); v1.w = packh2(im[6], im[7]);
        v2.x = packh2(im[0]-re[0], im[1]-re[1]); v2.y = packh2(im[2]-re[2], im[3]-re[3]);
        v2.z = packh2(im[4]-re[4], im[5]-re[5]); v2.w = packh2(im[6]-re[6], im[7]-re[7]);

        g_AH[obase + x]               = v0;
        g_AH[obase + ASTRIDE + x]     = v1;
        g_AH[obase + 2 * ASTRIDE + x] = v2;
    }
}

// ============================================================================
// GEMM core body (shared by gemm_big and gemm_frag)
// ============================================================================
#define STAGES 4
#define STG_BYTES 16384
#define GSMEM (STAGES * STG_BYTES)

#define GEMM_BODY(At, Bt, Cb, Nld, n0, kIters)                                 \
    const int wm4 = (wid & 1) * 4;                                             \
    const int wn4 = (wid >> 1) * 4;                                            \
    float acc[4][8][4];                                                        \
    _Pragma("unroll")                                                          \
    for (int a = 0; a < 4; a++)                                                \
        _Pragma("unroll")                                                      \
        for (int b2 = 0; b2 < 8; b2++)                                         \
            _Pragma("unroll")                                                  \
            for (int c = 0; c < 4; c++) acc[a][b2][c] = 0.0f;                  \
    ISSUE(0);                                                                  \
    asm volatile("cp.async.commit_group;" ::: "memory");                       \
    ISSUE(1);                                                                  \
    asm volatile("cp.async.commit_group;" ::: "memory");                       \
    ISSUE(2);                                                                  \
    asm volatile("cp.async.commit_group;" ::: "memory");                       \
    uint4 af[2][4], bf[2][4];                                                  \
    for (int kb = 0; kb < kIters; ++kb) {                                      \
        asm volatile("cp.async.wait_group 2;" ::: "memory");                   \
        __syncthreads();                                                       \
        const uint4* As = smu + (kb % STAGES) * 1024;                          \
        const uint4* Bs = As + 512;                                            \
        _Pragma("unroll")                                                      \
        for (int t = 0; t < 4; ++t) {                                          \
            af[0][t] = As[((wm4 + t) * 2) * 32 + lane];                        \
            bf[0][t] = Bs[((wn4 + t) * 2) * 32 + lane];                        \
        }                                                                      \
        _Pragma("unroll")                                                      \
        for (int ks = 0; ks < 2; ++ks) {                                       \
            const int cur = ks;                                                \
            if (ks == 0) {                                                     \
                _Pragma("unroll")                                              \
                for (int t = 0; t < 4; ++t) {                                  \
                    af[1][t] = As[((wm4 + t) * 2 + 1) * 32 + lane];            \
                    bf[1][t] = Bs[((wn4 + t) * 2 + 1) * 32 + lane];            \
                }                                                              \
            }                                                                  \
            _Pragma("unroll")                                                  \
            for (int tm = 0; tm < 4; ++tm) {                                   \
                const uint32_t* a = (const uint32_t*)&af[cur][tm];             \
                _Pragma("unroll")                                              \
                for (int p = 0; p < 4; ++p) {                                  \
                    const uint32_t* bu = (const uint32_t*)&bf[cur][p];         \
                    mma_f16(acc[tm][p * 2],     a, bu[0], bu[1]);              \
                    mma_f16(acc[tm][p * 2 + 1], a, bu[2], bu[3]);              \
                }                                                              \
            }                                                                  \
        }                                                                      \
        if (kb + 3 < kIters) ISSUE(kb + 3);                                    \
        asm volatile("cp.async.commit_group;" ::: "memory");                   \
    }                                                                          \
    _Pragma("unroll")                                                          \
    for (int tm = 0; tm < 4; ++tm) {                                           \
        _Pragma("unroll")                                                      \
        for (int tn = 0; tn < 8; ++tn) {                                       \
            const int m0 = mp * 128 + (wid & 1) * 64 + tm * 16 + grp;          \
            const int nn = n0 + (wid >> 1) * 64 + tn * 8 + tig * 2;            \
            *(float2*)&Cb[(size_t)m0 * Nld + nn]       = make_float2(acc[tm][tn][0], acc[tm][tn][1]); \
            *(float2*)&Cb[(size_t)(m0 + 8) * Nld + nn] = make_float2(acc[tm][tn][2], acc[tm][tn][3]); \
        }                                                                      \
    }

#define ISSUE(kb) do {                                                         \
    const uint32_t _st = sbase + ((kb) % STAGES) * STG_BYTES;                  \
    const uint4* _sa = At + (size_t)(kb) * TU4;                                \
    const uint4* _sb = Bt + (size_t)(kb) * TU4;                                \
    _Pragma("unroll")                                                          \
    for (int _i = 0; _i < 4; _i++) {                                           \
        const int _o = tid + _i * 128;                                         \
        cp16s(_st + _o * 16, _sa + _o);                                        \
        cp16s(_st + 8192 + _o * 16, _sb + _o);                                 \
    }                                                                          \
} while (0)

// gemm_big: panels 0-31 = zr (K=4096), panels 32-47 = x_h (K=2048)
__global__ __launch_bounds__(128, 2) void gemm_big()
{
    extern __shared__ uint4 smu[];
    const uint32_t sbase = smem_u32(smu);
    const int tid = threadIdx.x, wid = tid >> 5, lane = tid & 31;
    const int grp = lane >> 2, tig = lane & 3;
    const int mp = blockIdx.y;
    const int batch = blockIdx.z;
    const int panel = blockIdx.x;

    const uint4* At = g_AH + (size_t)(mp * 3 + batch) * ASTRIDE;
    const uint4* Bt;
    float* Cb;
    int kIters, Nld, n0;
    if (panel < 32) {
        Bt = g_WZR + (size_t)(panel * 3 + batch) * ASTRIDE;
        Cb = g_ZR + (size_t)batch * 1024 * 4096;
        kIters = 128; Nld = 4096; n0 = panel * 128;
    } else {
        Bt = g_WH + (size_t)((panel - 32) * 3 + batch) * HSTRIDE;
        Cb = g_XH + (size_t)batch * 1024 * 2048;
        kIters = 64; Nld = 2048; n0 = (panel - 32) * 128;
    }
    GEMM_BODY(At, Bt, Cb, Nld, n0, kIters)
}

// gemm_frag: HH GEMM (A=RHF, B=WRH), split-K x2 via blockIdx.z
__global__ __launch_bounds__(128, 2) void gemm_frag(
    const uint4* __restrict__ Ap, const uint4* __restrict__ Bp,
    float* __restrict__ C, int Nld, int kIters)
{
    extern __shared__ uint4 smu[];
    const uint32_t sbase = smem_u32(smu);
    const int tid = threadIdx.x, wid = tid >> 5, lane = tid & 31;
    const int grp = lane >> 2, tig = lane & 3;
    const int mp = blockIdx.y;
    const int z = blockIdx.z;
    const int batch = z % 3, half_ = z / 3;
    const int panel = blockIdx.x;
    const int kO = half_ * kIters;

    const uint4* At = Ap + (size_t)(mp * 3 + batch) * BSTR + (size_t)kO * TU4;
    const uint4* Bt = Bp + (size_t)(panel * 3 + batch) * BSTR + (size_t)kO * TU4;
    float* Cb = C + (size_t)z * 1024 * Nld;
    const int n0 = panel * 128;
    GEMM_BODY(At, Bt, Cb, Nld, n0, kIters)
}

// ---------------------------------------------------------------- elementwise
__device__ __forceinline__ float hsig(float x) {
    return fminf(fmaxf(0.2f * x + 0.5f, 0.0f), 1.0f);
}

__global__ void ew_zr(const float* __restrict__ ZR, const float* __restrict__ h,
                      const float* __restrict__ rb, const float* __restrict__ ib,
                      float* __restrict__ Z, __half* __restrict__ RHp)
{
    const int i = blockIdx.x * blockDim.x + threadIdx.x;
    const int m = i >> 9;
    const int jj = (i & 511) << 2;

    const size_t PX = (size_t)1024 * 4096;
    const float* Z1 = ZR + (size_t)m * 4096;

    float4 p1z = *(const float4*)&Z1[jj],        p2z = *(const float4*)&Z1[PX + jj],
           p3z = *(const float4*)&Z1[2*PX + jj];
    float4 p1r = *(const float4*)&Z1[2048 + jj], p2r = *(const float4*)&Z1[PX + 2048 + jj],
           p3r = *(const float4*)&Z1[2*PX + 2048 + jj];

    float4 hre = *(const float4*)&h[(size_t)m * 4096 + jj];
    float4 him = *(const float4*)&h[(size_t)m * 4096 + 2048 + jj];
    float4 bzr = *(const float4*)&rb[jj],        bzi = *(const float4*)&ib[jj];
    float4 brr = *(const float4*)&rb[2048 + jj], bri = *(const float4*)&ib[2048 + jj];

    float zre[4], zim[4], vre[4], vim[4];
#pragma unroll
    for (int c = 0; c < 4; c++) {
        float P1z = (&p1z.x)[c], P2z = (&p2z.x)[c], P3z = (&p3z.x)[c];
        float P1r = (&p1r.x)[c], P2r = (&p2r.x)[c], P3r = (&p3r.x)[c];
        zre[c] = hsig(P1z + P2z + (&bzr.x)[c]);
        zim[c] = hsig(P3z + P1z - P2z + (&bzi.x)[c]);
        float rre = hsig(P1r + P2r + (&brr.x)[c]);
        float rim = hsig(P3r + P1r - P2r + (&bri.x)[c]);
        vre[c] = rre * (&hre.x)[c];
        vim[c] = rim * (&him.x)[c];
    }

    *(float4*)&Z[(size_t)m * 4096 + jj]        = make_float4(zre[0], zre[1], zre[2], zre[3]);
    *(float4*)&Z[(size_t)m * 4096 + 2048 + jj] = make_float4(zim[0], zim[1], zim[2], zim[3]);

    const int mp = m >> 7, m16 = (m >> 4) & 7;
    const int rr = m & 15, grpm = rr & 7, hi = rr >> 3;
    const int kb = jj >> 5, k16 = (jj >> 4) & 1;
    const int jmk = jj & 15, tig0 = (jmk & 7) >> 1, hiK = jmk >> 3;
    const int pos = hiK * 4 + hi * 2;
    const size_t HBSTR = (size_t)64 * 4096;
    size_t base = ((size_t)(mp * 3) * 64 + kb) * 4096
                + ((size_t)((m16 * 2 + k16) * 32 + grpm * 4) * 8) + pos;

    __half2 a0 = __floats2half2_rn(vre[0], vre[1]);
    __half2 a1 = __floats2half2_rn(vre[2], vre[3]);
    __half2 b0 = __floats2half2_rn(vim[0], vim[1]);
    __half2 b1 = __floats2half2_rn(vim[2], vim[3]);
    __half2 c0 = __floats2half2_rn(vim[0]-vre[0], vim[1]-vre[1]);
    __half2 c1 = __floats2half2_rn(vim[2]-vre[2], vim[3]-vre[3]);

    __half* RH = RHp;
    *(__half2*)&RH[base + (size_t)tig0 * 8]                   = a0;
    *(__half2*)&RH[base + (size_t)(tig0 + 1) * 8]             = a1;
    *(__half2*)&RH[base + HBSTR + (size_t)tig0 * 8]           = b0;
    *(__half2*)&RH[base + HBSTR + (size_t)(tig0 + 1) * 8]     = b1;
    *(__half2*)&RH[base + 2 * HBSTR + (size_t)tig0 * 8]       = c0;
    *(__half2*)&RH[base + 2 * HBSTR + (size_t)(tig0 + 1) * 8] = c1;
}

__global__ void ew_out(const float* __restrict__ XH, const float* __restrict__ R,
                       const float* __restrict__ h, const float* __restrict__ rb,
                       const float* __restrict__ ib, const float* __restrict__ Z,
                       float* __restrict__ out)
{
    const int i = blockIdx.x * blockDim.x + threadIdx.x;
    const int m = i >> 9;
    const int jj = (i & 511) << 2;

    const size_t HX = (size_t)1024 * 2048, RX = (size_t)1024 * 2048;
    const float* X1 = XH + (size_t)m * 2048;
    const float* R1 = R + (size_t)m * 2048;

    float4 p1 = *(const float4*)&X1[jj],      p2 = *(const float4*)&X1[HX + jj],
           p3 = *(const float4*)&X1[2*HX + jj];
    float4 r1a = *(const float4*)&R1[jj],        r1b = *(const float4*)&R1[3*RX + jj];
    float4 r2a = *(const float4*)&R1[RX + jj],   r2b = *(const float4*)&R1[4*RX + jj];
    float4 r3a = *(const float4*)&R1[2*RX + jj], r3b = *(const float4*)&R1[5*RX + jj];

    float4 hre = *(const float4*)&h[(size_t)m * 4096 + jj];
    float4 him = *(const float4*)&h[(size_t)m * 4096 + 2048 + jj];
    float4 zre = *(const float4*)&Z[(size_t)m * 4096 + jj];
    float4 zim = *(const float4*)&Z[(size_t)m * 4096 + 2048 + jj];
    float4 bhr = *(const float4*)&rb[4096 + jj], bhi = *(const float4*)&ib[4096 + jj];

    float ore[4], oim[4];
#pragma unroll
    for (int c = 0; c < 4; c++) {
        float A1 = (&p1.x)[c], A2 = (&p2.x)[c], A3 = (&p3.x)[c];
        float B1 = (&r1a.x)[c] + (&r1b.x)[c];
        float B2 = (&r2a.x)[c] + (&r2b.x)[c];
        float B3 = (&r3a.x)[c] + (&r3b.x)[c];
        float xre = A1 + A2 + (&bhr.x)[c] + B1 + B2;
        float xim = A3 + A1 - A2 + (&bhi.x)[c] + B3 + B1 - B2;
        float tre = tanhf(xre), tim = tanhf(xim);
        float Zr = (&zre.x)[c], Zi = (&zim.x)[c];
        ore[c] = Zr * (&hre.x)[c] + (1.0f - Zr) * tre;
        oim[c] = Zi * (&him.x)[c] + (1.0f - Zi) * tim;
    }
    *(float4*)&out[(size_t)m * 4096 + jj]        = make_float4(ore[0], ore[1], ore[2], ore[3]);
    *(float4*)&out[(size_t)m * 4096 + 2048 + jj] = make_float4(oim[0], oim[1], oim[2], oim[3]);
}

// --------------------------------------------------------------------- launch
extern "C" void kernel_launch(void* const* d_in, const int* in_sizes, int n_in,
                              void* d_out, int out_size)
{
    const float* inputs = (const float*)d_in[0];
    const float* h_tm1  = (const float*)d_in[1];
    const float* rk     = (const float*)d_in[2];
    const float* ik     = (const float*)d_in[3];
    const float* rrk    = (const float*)d_in[4];
    const float* irk    = (const float*)d_in[5];
    const float* rb     = (const float*)d_in[6];
    const float* ib     = (const float*)d_in[7];
    float* out = (float*)d_out;

    uint4 *pRHF, *pWRH;
    float *pZR, *pXH, *pR, *pZ;
    cudaGetSymbolAddress((void**)&pRHF, g_RHF);
    cudaGetSymbolAddress((void**)&pWRH, g_WRH);
    cudaGetSymbolAddress((void**)&pZR,  g_ZR);
    cudaGetSymbolAddress((void**)&pXH,  g_XH);
    cudaGetSymbolAddress((void**)&pR,   g_R);
    cudaGetSymbolAddress((void**)&pZ,   g_Z);

    cudaFuncSetAttribute(gemm_big,  cudaFuncAttributeMaxDynamicSharedMemorySize, GSMEM);
    cudaFuncSetAttribute(gemm_frag, cudaFuncAttributeMaxDynamicSharedMemorySize, GSMEM);

    cudaStream_t s1;
    cudaStreamCreateWithFlags(&s1, cudaStreamNonBlocking);
    cudaEvent_t eF, eA;
    cudaEventCreateWithFlags(&eF, cudaEventDisableTiming);
    cudaEventCreateWithFlags(&eA, cudaEventDisableTiming);

    // fork: prep_a on side stream, prep_w on main stream (concurrent)
    cudaEventRecord(eF, 0);
    cudaStreamWaitEvent(s1, eF, 0);
    prep_a<<<1024, 256, 0, s1>>>(inputs, h_tm1);
    cudaEventRecord(eA, s1);

    prep_w<<<6144, 256>>>(rk, ik, rrk, irk);

    // join: big GEMM needs both
    cudaStreamWaitEvent(0, eA, 0);
    gemm_big<<<dim3(48, 8, 3), 128, GSMEM>>>();
    ew_zr<<<2048, 256>>>(pZR, h_tm1, rb, ib, pZ, (__half*)pRHF);
    gemm_frag<<<dim3(16, 8, 6), 128, GSMEM>>>(pRHF, pWRH, pR, 2048, 32);
    ew_out<<<2048, 256>>>(pXH, pR, h_tm1, rb, ib, pZ, out);
}